// round 14
// baseline (speedup 1.0000x reference)
#include <cuda_runtime.h>
#include <cuda_fp16.h>
#include <math.h>
#include <stdint.h>

// ---------------- problem constants ----------------
#define BB    4
#define SS    2048
#define HIDC  768
#define NH    6
#define HD    64
#define AHSZ  384
#define KW    9
#define MROWS (BB*SS)      // 8192
#define NZ    (BB*NH)      // 24
#define HK    (NH*KW)      // 54

// ---------------- scratch ----------------
__device__ __half g_hidden_h[MROWS*HIDC];
__device__ __half g_qh[MROWS*AHSZ];
__device__ __half g_kh[MROWS*AHSZ];
__device__ __half g_vh[MROWS*AHSZ];
__device__ float  g_q [MROWS*AHSZ];      // fp32 q for FILT elementwise
__device__ float  g_v [MROWS*AHSZ];      // fp32 v for convout
__device__ __half g_dwh[MROWS*HIDC];
__device__ float  g_ks[MROWS*AHSZ];
__device__ __half g_convh[MROWS*AHSZ];
__device__ float  g_logits[MROWS*HK];
__device__ __half g_attn_h[MROWS*AHSZ];
// fp16 weight copies
__device__ __half g_Wq_h[HIDC*AHSZ];
__device__ __half g_Wk_h[HIDC*AHSZ];
__device__ __half g_Wv_h[HIDC*AHSZ];
__device__ __half g_pwt_h[HIDC*AHSZ];    // pw transposed to [c][o]
__device__ __half g_Wsl_h[AHSZ*AHSZ];
__device__ __half g_Wcl_h[AHSZ*AHSZ];
__device__ __half g_Wak_h[AHSZ*64];      // padded 54 -> 64
// fallbacks
__device__ float g_attn_fb[MROWS*AHSZ];
__device__ float g_sco_fb [(size_t)NZ*SS*SS];

// ---------------- mma / ldmatrix / cp.async helpers ----------------
__device__ __forceinline__ void mma_f16(float* d, const unsigned* a, unsigned b0, unsigned b1) {
    asm volatile(
        "mma.sync.aligned.m16n8k16.row.col.f32.f16.f16.f32 "
        "{%0,%1,%2,%3}, {%4,%5,%6,%7}, {%8,%9}, {%0,%1,%2,%3};"
        : "+f"(d[0]), "+f"(d[1]), "+f"(d[2]), "+f"(d[3])
        : "r"(a[0]), "r"(a[1]), "r"(a[2]), "r"(a[3]), "r"(b0), "r"(b1));
}
__device__ __forceinline__ unsigned pack_f16(float lo, float hi) {
    unsigned r;
    asm("cvt.rn.f16x2.f32 %0, %1, %2;" : "=r"(r) : "f"(hi), "f"(lo));
    return r;
}
__device__ __forceinline__ void ldsm4(unsigned* r, unsigned addr) {
    asm volatile("ldmatrix.sync.aligned.m8n8.x4.shared.b16 {%0,%1,%2,%3}, [%4];"
        : "=r"(r[0]), "=r"(r[1]), "=r"(r[2]), "=r"(r[3]) : "r"(addr));
}
__device__ __forceinline__ void ldsm4t(unsigned* r, unsigned addr) {
    asm volatile("ldmatrix.sync.aligned.m8n8.x4.trans.shared.b16 {%0,%1,%2,%3}, [%4];"
        : "=r"(r[0]), "=r"(r[1]), "=r"(r[2]), "=r"(r[3]) : "r"(addr));
}
__device__ __forceinline__ unsigned s2u(const void* p) {
    return (unsigned)__cvta_generic_to_shared(p);
}
__device__ __forceinline__ void cpa16(unsigned dst, const void* src) {
    asm volatile("cp.async.ca.shared.global [%0], [%1], 16;" :: "r"(dst), "l"(src));
}
__device__ __forceinline__ void cpa_commit() { asm volatile("cp.async.commit_group;"); }
template <int N>
__device__ __forceinline__ void cpa_wait() { asm volatile("cp.async.wait_group %0;" :: "n"(N)); }

// ---------------- prep kernels ----------------
__global__ void __launch_bounds__(256) cvt_multi(
    const float4* s0, __half2* d0, int e0,
    const float4* s1, __half2* d1, int e1,
    const float4* s2, __half2* d2, int e2,
    const float4* s3, __half2* d3, int e3,
    const float4* s4, __half2* d4, int e4,
    const float4* s5, __half2* d5, int e5)
{
    const int i = blockIdx.x * 256 + threadIdx.x;
    const float4* s; __half2* d; int base;
    if      (i < e0) { s = s0; d = d0; base = 0;  }
    else if (i < e1) { s = s1; d = d1; base = e0; }
    else if (i < e2) { s = s2; d = d2; base = e1; }
    else if (i < e3) { s = s3; d = d3; base = e2; }
    else if (i < e4) { s = s4; d = d4; base = e3; }
    else if (i < e5) { s = s5; d = d5; base = e4; }
    else return;
    const int j = i - base;
    const float4 x = s[j];
    d[2 * j + 0] = __floats2half2_rn(x.x, x.y);
    d[2 * j + 1] = __floats2half2_rn(x.z, x.w);
}

__global__ void transpose_pw(const float* __restrict__ pw, __half* __restrict__ out)
{
    __shared__ float t[32][33];
    const int c0 = blockIdx.x * 32, o0 = blockIdx.y * 32;
    for (int i = threadIdx.y; i < 32; i += 8)
        t[i][threadIdx.x] = pw[(size_t)(o0 + i) * HIDC + c0 + threadIdx.x];
    __syncthreads();
    for (int i = threadIdx.y; i < 32; i += 8)
        out[(size_t)(c0 + i) * AHSZ + o0 + threadIdx.x] = __float2half(t[threadIdx.x][i]);
}

__global__ void pad_wak(const float* __restrict__ Wak, __half* __restrict__ out)
{
    const int r = blockIdx.x, t = threadIdx.x;  // 384 x 64
    out[r * 64 + t] = (t < HK) ? __float2half(Wak[r * HK + t]) : __half(0.f);
}

// =================== fp16 hgemm v3: 256x64x32 tile, 256 thr, 8 warps, 2 m-tiles/warp ===================
// Fragment sharing (ldsm/mma 0.375) WITH 8 warps for latency hiding.
enum { H_QKV = 0, H_NT = 1, H_MIX = 3 };
#define A_P 40   // halves pitch of A tile (32+8)
#define B_P 72   // halves pitch of B tile (64+8)
#define MT  256  // M tile
#define A_STAGE_B (MT*A_P*2)        // 20480 bytes per A stage
#define B_STAGE_B (32*B_P*2)        // 4608 bytes per B stage
#define HG_SMEM (2*A_STAGE_B + 2*B_STAGE_B)   // 50176 bytes

template <int MODE>
__global__ void __launch_bounds__(256) hgemm(
    const __half* __restrict__ Ah0, const __half* __restrict__ Ah1,
    const __half* __restrict__ B0, const __half* __restrict__ B1, const __half* __restrict__ B2,
    const float* __restrict__ b0p, const float* __restrict__ b1p, const float* __restrict__ b2p,
    float* C0f, float* C1f, float* C2f,
    __half* C0h, __half* C1h, __half* C2h,
    int Kdim, int lda, int ldw, int ldc)
{
    extern __shared__ char smc[];
    const unsigned sb = s2u(smc);
    const unsigned b_base = sb + 2 * A_STAGE_B;

    const int tid = threadIdx.x;
    const int w = tid >> 5, lane = tid & 31;
    const int lq = lane >> 2, lr = lane & 3;
    const int m0 = blockIdx.y * MT;
    const int n0 = blockIdx.x * 64;

    const __half* A = Ah0;
    const __half* B = B0;
    const float* bias = b0p;
    float* Cf = C0f;
    __half* Ch = C0h;
    if constexpr (MODE == H_QKV) {
        const int z = blockIdx.z;
        B    = (z == 0) ? B0 : ((z == 1) ? B1 : B2);
        bias = (z == 0) ? b0p : ((z == 1) ? b1p : b2p);
        Cf   = (z == 0) ? C0f : ((z == 1) ? C1f : C2f);
        Ch   = (z == 0) ? C0h : ((z == 1) ? C1h : C2h);
    }
    if constexpr (MODE == H_MIX) {
        const int z = blockIdx.z;
        A = z ? Ah1 : Ah0;
        B = z ? B1 : B0;
        bias = z ? b1p : b0p;
        Cf = C0f + z * AHSZ;
    }

    float c[2][8][4];
#pragma unroll
    for (int mi = 0; mi < 2; mi++)
#pragma unroll
        for (int j = 0; j < 8; j++)
#pragma unroll
            for (int r = 0; r < 4; r++) c[mi][j][r] = 0.f;

    // ldmatrix lane addresses: A frags for both m16 tiles; B frags shared across m-tiles
    unsigned a_lane_b[2];
#pragma unroll
    for (int mi = 0; mi < 2; mi++)
        a_lane_b[mi] = sb +
            (unsigned)(((w * 32 + mi * 16 + (lane & 15)) * A_P + (lane >> 4) * 8) * 2);
    const unsigned b_lane_b = b_base +
        (unsigned)((((lane & 7) + ((lane >> 3) & 1) * 8) * B_P + ((lane >> 3) >> 1) * 8) * 2);

    // staging (256 threads): A row tid (32 halves = 4x cpa16); B row tid>>3, 8-half chunk
    const int ar = tid;
    const int br = tid >> 3, bcb = (tid & 7) * 8;

    const unsigned a_st = sb + (unsigned)(ar * A_P * 2);
    const unsigned b_st = b_base + (unsigned)((br * B_P + bcb) * 2);

    const int NIT = Kdim / 32;
    {
        const __half* ap = &A[(size_t)(m0 + ar) * lda];
#pragma unroll
        for (int u = 0; u < 4; u++) cpa16(a_st + u * 16, ap + u * 8);
        cpa16(b_st, &B[(size_t)br * ldw + n0 + bcb]);
        cpa_commit();
    }

    for (int it = 0; it < NIT; it++) {
        if (it + 1 < NIT) {
            const int k0 = (it + 1) * 32;
            const unsigned s = (unsigned)((it + 1) & 1);
            const __half* ap = &A[(size_t)(m0 + ar) * lda + k0];
#pragma unroll
            for (int u = 0; u < 4; u++) cpa16(a_st + s * A_STAGE_B + u * 16, ap + u * 8);
            cpa16(b_st + s * B_STAGE_B, &B[(size_t)(k0 + br) * ldw + n0 + bcb]);
            cpa_commit();
            cpa_wait<1>();
        } else {
            cpa_wait<0>();
        }
        __syncthreads();

        const unsigned s = (unsigned)(it & 1);
        const unsigned b_lane = b_lane_b + s * B_STAGE_B;
#pragma unroll
        for (int kc = 0; kc < 2; kc++) {
            unsigned af[2][4];
#pragma unroll
            for (int mi = 0; mi < 2; mi++)
                ldsm4(af[mi], a_lane_b[mi] + s * A_STAGE_B + (unsigned)(kc * 32));
#pragma unroll
            for (int nb = 0; nb < 4; nb++) {
                unsigned kb[4];
                ldsm4t(kb, b_lane + (unsigned)((kc * 16 * B_P + nb * 16) * 2));
#pragma unroll
                for (int mi = 0; mi < 2; mi++) {
                    mma_f16(c[mi][2 * nb],     af[mi], kb[0], kb[1]);
                    mma_f16(c[mi][2 * nb + 1], af[mi], kb[2], kb[3]);
                }
            }
        }
        __syncthreads();
    }

    // ---- epilogue ----
#pragma unroll
    for (int mi = 0; mi < 2; mi++) {
        const int rowA = m0 + w * 32 + mi * 16 + lq;
#pragma unroll
        for (int j = 0; j < 8; j++) {
            const int n = n0 + j * 8 + 2 * lr;
            const float bj0 = bias[n], bj1 = bias[n + 1];
            const float v0 = c[mi][j][0] + bj0, v1 = c[mi][j][1] + bj1;
            const float v2 = c[mi][j][2] + bj0, v3 = c[mi][j][3] + bj1;
            if (Cf) {
                *reinterpret_cast<float2*>(&Cf[(size_t)rowA * ldc + n]) = make_float2(v0, v1);
                *reinterpret_cast<float2*>(&Cf[(size_t)(rowA + 8) * ldc + n]) = make_float2(v2, v3);
            }
            if constexpr (MODE == H_QKV) {
                *reinterpret_cast<unsigned*>(&Ch[(size_t)rowA * ldc + n]) = pack_f16(v0, v1);
                *reinterpret_cast<unsigned*>(&Ch[(size_t)(rowA + 8) * ldc + n]) = pack_f16(v2, v3);
            }
        }
    }
}

// =================== FILT: (ks*q) @ Wak + bak (R13-proven 128-thr variant) ===================
__global__ void __launch_bounds__(128) hgemm_filt(
    const float* __restrict__ Af0, const float* __restrict__ Af1,
    const __half* __restrict__ B0, const float* __restrict__ bias, float* __restrict__ Cf)
{
    __shared__ __half Ash[128 * A_P];
    __shared__ __half Bsh[32 * B_P];

    const int tid = threadIdx.x;
    const int w = tid >> 5, lane = tid & 31;
    const int lq = lane >> 2, lr = lane & 3;
    const int m0 = blockIdx.y * 128;

    float c[2][8][4];
#pragma unroll
    for (int mi = 0; mi < 2; mi++)
#pragma unroll
        for (int j = 0; j < 8; j++)
#pragma unroll
            for (int r = 0; r < 4; r++) c[mi][j][r] = 0.f;

    unsigned a_lane[2];
#pragma unroll
    for (int mi = 0; mi < 2; mi++)
        a_lane[mi] = s2u(Ash) +
            (unsigned)(((w * 32 + mi * 16 + (lane & 15)) * A_P + (lane >> 4) * 8) * 2);
    const unsigned b_lane = s2u(Bsh) +
        (unsigned)((((lane & 7) + ((lane >> 3) & 1) * 8) * B_P + ((lane >> 3) >> 1) * 8) * 2);

    const int ar = tid;
    const int br = tid >> 2, bcb = (tid & 3) * 16;

    for (int k0 = 0; k0 < AHSZ; k0 += 32) {
        {
            const float* pa = &Af0[(size_t)(m0 + ar) * AHSZ + k0];
            const float* pb = &Af1[(size_t)(m0 + ar) * AHSZ + k0];
            __half2* dst = reinterpret_cast<__half2*>(&Ash[ar * A_P]);
#pragma unroll
            for (int u = 0; u < 8; u++) {
                const float4 xa = *reinterpret_cast<const float4*>(pa + u * 4);
                const float4 xb = *reinterpret_cast<const float4*>(pb + u * 4);
                dst[2 * u + 0] = __floats2half2_rn(xa.x * xb.x, xa.y * xb.y);
                dst[2 * u + 1] = __floats2half2_rn(xa.z * xb.z, xa.w * xb.w);
            }
        }
        {
            const __half* bp = &B0[(size_t)(k0 + br) * 64 + bcb];
            *reinterpret_cast<uint4*>(&Bsh[br * B_P + bcb]) =
                *reinterpret_cast<const uint4*>(bp);
            *reinterpret_cast<uint4*>(&Bsh[br * B_P + bcb + 8]) =
                *reinterpret_cast<const uint4*>(bp + 8);
        }
        __syncthreads();

#pragma unroll
        for (int kc = 0; kc < 2; kc++) {
            unsigned af[2][4];
#pragma unroll
            for (int mi = 0; mi < 2; mi++)
                ldsm4(af[mi], a_lane[mi] + (unsigned)(kc * 32));
#pragma unroll
            for (int nb = 0; nb < 4; nb++) {
                unsigned kb[4];
                ldsm4t(kb, b_lane + (unsigned)((kc * 16 * B_P + nb * 16) * 2));
#pragma unroll
                for (int mi = 0; mi < 2; mi++) {
                    mma_f16(c[mi][2 * nb],     af[mi], kb[0], kb[1]);
                    mma_f16(c[mi][2 * nb + 1], af[mi], kb[2], kb[3]);
                }
            }
        }
        __syncthreads();
    }

#pragma unroll
    for (int mi = 0; mi < 2; mi++) {
        const int rowA = m0 + w * 32 + mi * 16 + lq;
#pragma unroll
        for (int j = 0; j < 8; j++) {
            const int n = j * 8 + 2 * lr;
            if (n < HK) {
                const float bj0 = bias[n], bj1 = bias[n + 1];
                *reinterpret_cast<float2*>(&Cf[(size_t)rowA * HK + n]) =
                    make_float2(c[mi][j][0] + bj0, c[mi][j][1] + bj1);
                *reinterpret_cast<float2*>(&Cf[(size_t)(rowA + 8) * HK + n]) =
                    make_float2(c[mi][j][2] + bj0, c[mi][j][3] + bj1);
            }
        }
    }
}

// =================== fused flash attention v4 (R11/R13 proven) ===================
#define FQ_P 72
#define KV_STAGE (64*FQ_P*2)
#define FA_SMEM_B (4*KV_STAGE + SS*4)

__global__ void __launch_bounds__(128, 2) fattn_k(
    const __half* __restrict__ qh, const __half* __restrict__ kh, const __half* __restrict__ vh,
    const float* __restrict__ amask, float* __restrict__ scores,
    float* __restrict__ attn, __half* __restrict__ attnh)
{
    extern __shared__ char smc[];
    __half* Qh = (__half*)smc;
    __half* Ksh = (__half*)smc;
    __half* Vsh = (__half*)(smc + 2 * KV_STAGE);
    float* msk = (float*)(smc + 4 * KV_STAGE);

    const int tid  = threadIdx.x;
    const int w    = tid >> 5, lane = tid & 31;
    const int lq   = lane >> 2, lr = lane & 3;
    const int m0   = blockIdx.x * 128;
    const int z    = blockIdx.y, b = z / NH, h = z % NH;

    {
        const float4* s4 = reinterpret_cast<const float4*>(amask + (size_t)b * SS);
        float4* d4 = reinterpret_cast<float4*>(msk);
        for (int i = tid; i < SS / 4; i += 128) d4[i] = s4[i];
    }
    {
        const __half* qp = qh + ((size_t)(b * SS + m0 + tid)) * AHSZ + h * HD;
        uint4* dst = reinterpret_cast<uint4*>(&Qh[tid * FQ_P]);
#pragma unroll
        for (int u = 0; u < 8; u++) dst[u] = *reinterpret_cast<const uint4*>(qp + u * 8);
    }
    __syncthreads();

    unsigned Qa[2][4][4];
#pragma unroll
    for (int mi = 0; mi < 2; mi++) {
        const unsigned q_lane = s2u(Qh) +
            (unsigned)(((w * 32 + mi * 16 + (lane & 15)) * FQ_P + (lane >> 4) * 8) * 2);
#pragma unroll
        for (int kc = 0; kc < 4; kc++) ldsm4(Qa[mi][kc], q_lane + (unsigned)(kc * 32));
    }
    __syncthreads();

    float o[2][8][4];
#pragma unroll
    for (int mi = 0; mi < 2; mi++)
#pragma unroll
        for (int d = 0; d < 8; d++)
#pragma unroll
            for (int r = 0; r < 4; r++) o[mi][d][r] = 0.f;
    float lacc[2][2] = {{0.f, 0.f}, {0.f, 0.f}};

    const __half* kbase = kh + (size_t)b * SS * AHSZ + h * HD;
    const __half* vbase = vh + (size_t)b * SS * AHSZ + h * HD;
    float* sco = scores + (size_t)z * SS * SS;

    const unsigned k_lane_b = s2u(Ksh) +
        (unsigned)((((lane & 15)) * FQ_P + (lane >> 4) * 8) * 2);
    const unsigned v_lane_b = s2u(Vsh) +
        (unsigned)((((lane & 7) + ((lane >> 3) & 1) * 8) * FQ_P + ((lane >> 3) >> 1) * 8) * 2);

    const int sr = tid >> 1;
    const unsigned scb = (unsigned)(tid & 1) * 64u;
    const unsigned k_st = s2u(Ksh) + (unsigned)(sr * FQ_P * 2) + scb;
    const unsigned v_st = s2u(Vsh) + (unsigned)(sr * FQ_P * 2) + scb;
    const int sco_h = (tid & 1) * 32;

    {
        const __half* kp = kbase + (size_t)sr * AHSZ + sco_h;
        const __half* vp = vbase + (size_t)sr * AHSZ + sco_h;
#pragma unroll
        for (int u = 0; u < 4; u++) {
            cpa16(k_st + u * 16, kp + u * 8);
            cpa16(v_st + u * 16, vp + u * 8);
        }
        cpa_commit();
    }

    for (int kt = 0; kt < 32; kt++) {
        const int n0 = kt * 64;
        if (kt < 31) {
            const unsigned s = (unsigned)((kt + 1) & 1) * KV_STAGE;
            const __half* kp = kbase + (size_t)(n0 + 64 + sr) * AHSZ + sco_h;
            const __half* vp = vbase + (size_t)(n0 + 64 + sr) * AHSZ + sco_h;
#pragma unroll
            for (int u = 0; u < 4; u++) {
                cpa16(k_st + s + u * 16, kp + u * 8);
                cpa16(v_st + s + u * 16, vp + u * 8);
            }
            cpa_commit();
            cpa_wait<1>();
        } else {
            cpa_wait<0>();
        }
        __syncthreads();

        const unsigned s = (unsigned)(kt & 1) * KV_STAGE;
        const unsigned k_lane = k_lane_b + s;
        const unsigned v_lane = v_lane_b + s;

#pragma unroll
        for (int kg = 0; kg < 4; kg++) {
            float c[2][2][4];
#pragma unroll
            for (int mi = 0; mi < 2; mi++)
#pragma unroll
                for (int jj = 0; jj < 2; jj++)
#pragma unroll
                    for (int r = 0; r < 4; r++) c[mi][jj][r] = 0.f;
#pragma unroll
            for (int kc = 0; kc < 4; kc++) {
                unsigned kb[4];
                ldsm4(kb, k_lane + (unsigned)((kg * 16 * FQ_P + kc * 16) * 2));
#pragma unroll
                for (int mi = 0; mi < 2; mi++) {
                    mma_f16(c[mi][0], Qa[mi][kc], kb[0], kb[2]);
                    mma_f16(c[mi][1], Qa[mi][kc], kb[1], kb[3]);
                }
            }

            unsigned pa[2][4];
#pragma unroll
            for (int mi = 0; mi < 2; mi++) {
                const int row0 = w * 32 + mi * 16 + lq;
#pragma unroll
                for (int jj = 0; jj < 2; jj++) {
                    const int colL = kg * 16 + jj * 8 + 2 * lr;
                    const float mk0 = msk[n0 + colL], mk1 = msk[n0 + colL + 1];
                    const float s0 = c[mi][jj][0] * 0.125f + mk0;
                    const float s1 = c[mi][jj][1] * 0.125f + mk1;
                    const float s2 = c[mi][jj][2] * 0.125f + mk0;
                    const float s3 = c[mi][jj][3] * 0.125f + mk1;
                    *reinterpret_cast<float2*>(&sco[(size_t)(m0 + row0) * SS + n0 + colL]) =
                        make_float2(s0, s1);
                    *reinterpret_cast<float2*>(&sco[(size_t)(m0 + row0 + 8) * SS + n0 + colL]) =
                        make_float2(s2, s3);
                    const float p0 = __expf(s0), p1 = __expf(s1);
                    const float p2 = __expf(s2), p3 = __expf(s3);
                    lacc[mi][0] += p0 + p1;
                    lacc[mi][1] += p2 + p3;
                    pa[mi][jj * 2 + 0] = pack_f16(p0, p1);
                    pa[mi][jj * 2 + 1] = pack_f16(p2, p3);
                }
            }

#pragma unroll
            for (int dp = 0; dp < 4; dp++) {
                unsigned vb[4];
                ldsm4t(vb, v_lane + (unsigned)((kg * 16 * FQ_P + dp * 16) * 2));
#pragma unroll
                for (int mi = 0; mi < 2; mi++) {
                    mma_f16(o[mi][2 * dp],     pa[mi], vb[0], vb[1]);
                    mma_f16(o[mi][2 * dp + 1], pa[mi], vb[2], vb[3]);
                }
            }
        }
        __syncthreads();
    }

#pragma unroll
    for (int mi = 0; mi < 2; mi++) {
        float l0 = lacc[mi][0], l1 = lacc[mi][1];
        l0 += __shfl_xor_sync(0xFFFFFFFFu, l0, 1);
        l0 += __shfl_xor_sync(0xFFFFFFFFu, l0, 2);
        l1 += __shfl_xor_sync(0xFFFFFFFFu, l1, 1);
        l1 += __shfl_xor_sync(0xFFFFFFFFu, l1, 2);
        const float inv0 = 1.f / l0, inv1 = 1.f / l1;
        const int row0 = w * 32 + mi * 16 + lq;
#pragma unroll
        for (int d = 0; d < 8; d++) {
            const int col = h * HD + d * 8 + 2 * lr;
            const size_t r0 = ((size_t)(b * SS + m0 + row0)) * AHSZ + col;
            const size_t r1 = ((size_t)(b * SS + m0 + row0 + 8)) * AHSZ + col;
            const float v0 = o[mi][d][0] * inv0, v1 = o[mi][d][1] * inv0;
            const float v2 = o[mi][d][2] * inv1, v3 = o[mi][d][3] * inv1;
            *reinterpret_cast<float2*>(&attn[r0]) = make_float2(v0, v1);
            *reinterpret_cast<float2*>(&attn[r1]) = make_float2(v2, v3);
            *reinterpret_cast<unsigned*>(&attnh[r0]) = pack_f16(v0, v1);
            *reinterpret_cast<unsigned*>(&attnh[r1]) = pack_f16(v2, v3);
        }
    }
}

// ---------------- depthwise conv: smem-staged ----------------
#define DW_POS 16
__global__ void __launch_bounds__(384) dwconv_k(const __half* __restrict__ xh,
                                                const float* __restrict__ dwk)
{
    __shared__ __half hsm[(DW_POS + 8) * HIDC];
    const int s0 = blockIdx.x * DW_POS;
    const int b  = blockIdx.y;
    const int tid = threadIdx.x;

    for (int idx = tid; idx < (DW_POS + 8) * (HIDC / 8); idx += 384) {
        const int row = idx / (HIDC / 8);
        const int cb  = (idx % (HIDC / 8)) * 8;
        const int sp  = s0 - 4 + row;
        uint4 val = make_uint4(0, 0, 0, 0);
        if (sp >= 0 && sp < SS)
            val = *reinterpret_cast<const uint4*>(&xh[((size_t)b * SS + sp) * HIDC + cb]);
        *reinterpret_cast<uint4*>(&hsm[row * HIDC + cb]) = val;
    }
    __syncthreads();

    const int c0 = tid * 2;
    float kw0[KW], kw1[KW];
#pragma unroll
    for (int tp = 0; tp < KW; tp++) {
        kw0[tp] = dwk[c0 * KW + tp];
        kw1[tp] = dwk[(c0 + 1) * KW + tp];
    }

    for (int ls = 0; ls < DW_POS; ls++) {
        float a0 = 0.f, a1 = 0.f;
#pragma unroll
        for (int tp = 0; tp < KW; tp++) {
            const float2 xv = __half22float2(
                *reinterpret_cast<const __half2*>(&hsm[(ls + tp) * HIDC + c0]));
            a0 += xv.x * kw0[tp];
            a1 += xv.y * kw1[tp];
        }
        *reinterpret_cast<__half2*>(&g_dwh[((size_t)b * SS + s0 + ls) * HIDC + c0]) =
            __floats2half2_rn(a0, a1);
    }
}

// ---------------- tap softmax + windowed value conv: smem-staged ----------------
#define CO_POS 16
__global__ void __launch_bounds__(384) convout_k()
{
    __shared__ float vsm[(CO_POS + 8) * AHSZ];
    __shared__ float filt[CO_POS][HK + 2];
    const int s0 = blockIdx.x * CO_POS;
    const int b  = blockIdx.y;
    const int tid = threadIdx.x;

    for (int idx = tid; idx < (CO_POS + 8) * (AHSZ / 4); idx += 384) {
        const int row = idx / (AHSZ / 4);
        const int cb  = (idx % (AHSZ / 4)) * 4;
        const int sp  = s0 - 4 + row;
        float4 val = make_float4(0.f, 0.f, 0.f, 0.f);
        if (sp >= 0 && sp < SS)
            val = *reinterpret_cast<const float4*>(&g_v[((size_t)b * SS + sp) * AHSZ + cb]);
        *reinterpret_cast<float4*>(&vsm[row * AHSZ + cb]) = val;
    }

    if (tid < CO_POS * NH) {
        const int ls = tid % CO_POS, h = tid / CO_POS;
        const size_t mrow = (size_t)(b * SS + s0 + ls) * HK + h * KW;
        float lg[KW];
        float mx = -1e30f;
#pragma unroll
        for (int i = 0; i < KW; i++) {
            lg[i] = g_logits[mrow + i];
            mx = fmaxf(mx, lg[i]);
        }
        float sum = 0.f;
#pragma unroll
        for (int i = 0; i < KW; i++) { lg[i] = __expf(lg[i] - mx); sum += lg[i]; }
        const float is = 1.f / sum;
#pragma unroll
        for (int i = 0; i < KW; i++) filt[ls][h * KW + i] = lg[i] * is;
    }
    __syncthreads();

    const int c = tid;
    const int hb = (c >> 6) * KW;
    for (int ls = 0; ls < CO_POS; ls++) {
        float acc = 0.f;
#pragma unroll
        for (int tp = 0; tp < KW; tp++)
            acc += vsm[(ls + tp) * AHSZ + c] * filt[ls][hb + tp];
        g_convh[((size_t)(b * SS + s0 + ls)) * AHSZ + c] = __float2half(acc);
    }
}

// ---------------- launch (serial, default stream) ----------------
extern "C" void kernel_launch(void* const* d_in, const int* in_sizes, int n_in,
                              void* d_out, int out_size)
{
    const float* hidden = (const float*)d_in[0];
    const float* amask  = (const float*)d_in[1];
    const float* Wq = (const float*)d_in[2];  const float* bq = (const float*)d_in[3];
    const float* Wk = (const float*)d_in[4];  const float* bk = (const float*)d_in[5];
    const float* Wv = (const float*)d_in[6];  const float* bv = (const float*)d_in[7];
    const float* dwk = (const float*)d_in[8];
    const float* pw  = (const float*)d_in[9]; const float* sepb = (const float*)d_in[10];
    const float* Wak = (const float*)d_in[11]; const float* bak = (const float*)d_in[12];
    const float* Wsl = (const float*)d_in[13]; const float* bsl = (const float*)d_in[14];
    const float* Wcl = (const float*)d_in[15]; const float* bcl = (const float*)d_in[16];

    __half *hidh, *qhp, *khp, *vhp, *dwh, *convh, *attnh;
    __half *wqh, *wkh, *wvh, *pwth, *wslh, *wclh, *wakh;
    float *qf, *vf, *ks, *lg, *attn_fb, *sco_fb;
    cudaGetSymbolAddress((void**)&hidh,  g_hidden_h);
    cudaGetSymbolAddress((void**)&qhp,   g_qh);
    cudaGetSymbolAddress((void**)&khp,   g_kh);
    cudaGetSymbolAddress((void**)&vhp,   g_vh);
    cudaGetSymbolAddress((void**)&qf,    g_q);
    cudaGetSymbolAddress((void**)&vf,    g_v);
    cudaGetSymbolAddress((void**)&dwh,   g_dwh);
    cudaGetSymbolAddress((void**)&ks,    g_ks);
    cudaGetSymbolAddress((void**)&convh, g_convh);
    cudaGetSymbolAddress((void**)&lg,    g_logits);
    cudaGetSymbolAddress((void**)&attnh, g_attn_h);
    cudaGetSymbolAddress((void**)&wqh,   g_Wq_h);
    cudaGetSymbolAddress((void**)&wkh,   g_Wk_h);
    cudaGetSymbolAddress((void**)&wvh,   g_Wv_h);
    cudaGetSymbolAddress((void**)&pwth,  g_pwt_h);
    cudaGetSymbolAddress((void**)&wslh,  g_Wsl_h);
    cudaGetSymbolAddress((void**)&wclh,  g_Wcl_h);
    cudaGetSymbolAddress((void**)&wakh,  g_Wak_h);
    cudaGetSymbolAddress((void**)&attn_fb, g_attn_fb);
    cudaGetSymbolAddress((void**)&sco_fb,  g_sco_fb);

    float* outp = (float*)d_out;
    const size_t CTX_SZ = (size_t)MROWS * HIDC;
    const size_t ATT_OFF = CTX_SZ;
    const size_t ATT_SZ  = (size_t)MROWS * AHSZ;
    const size_t SCO_OFF = ATT_OFF + ATT_SZ;
    const size_t SCO_SZ  = (size_t)NZ * SS * SS;
    float* attnp = ((size_t)out_size >= ATT_OFF + ATT_SZ) ? outp + ATT_OFF : attn_fb;
    float* scop  = ((size_t)out_size >= SCO_OFF + SCO_SZ) ? outp + SCO_OFF : sco_fb;

    // ---- prep: fused conversions + pw transpose + wak pad ----
    {
        const int n0 = MROWS * HIDC / 4;
        const int nw = HIDC * AHSZ / 4;
        const int nm = AHSZ * AHSZ / 4;
        const int e0 = n0, e1 = e0 + nw, e2 = e1 + nw, e3 = e2 + nw;
        const int e4 = e3 + nm, e5 = e4 + nm;
        cvt_multi<<<(e5 + 255) / 256, 256>>>(
            (const float4*)hidden, (__half2*)hidh, e0,
            (const float4*)Wq,  (__half2*)wqh,  e1,
            (const float4*)Wk,  (__half2*)wkh,  e2,
            (const float4*)Wv,  (__half2*)wvh,  e3,
            (const float4*)Wsl, (__half2*)wslh, e4,
            (const float4*)Wcl, (__half2*)wclh, e5);
    }
    transpose_pw<<<dim3(HIDC / 32, AHSZ / 32), dim3(32, 8)>>>(pw, pwth);
    pad_wak<<<AHSZ, 64>>>(Wak, wakh);

    // smem attrs for dynamic-smem hgemm
    cudaFuncSetAttribute(hgemm<H_QKV>, cudaFuncAttributeMaxDynamicSharedMemorySize, HG_SMEM);
    cudaFuncSetAttribute(hgemm<H_NT>,  cudaFuncAttributeMaxDynamicSharedMemorySize, HG_SMEM);
    cudaFuncSetAttribute(hgemm<H_MIX>, cudaFuncAttributeMaxDynamicSharedMemorySize, HG_SMEM);
    cudaFuncSetAttribute(fattn_k, cudaFuncAttributeMaxDynamicSharedMemorySize, FA_SMEM_B);

    // 1) fused QKV (fp16, 256-row tile, 8-warp fragment-sharing)
    hgemm<H_QKV><<<dim3(AHSZ / 64, MROWS / MT, 3), 256, HG_SMEM>>>(
        hidh, nullptr,
        wqh, wkh, wvh, bq, bk, bv,
        qf, nullptr, vf, qhp, khp, vhp,
        HIDC, HIDC, AHSZ, AHSZ);

    // 2) fused attention v4
    fattn_k<<<dim3(SS / 128, NZ), 128, FA_SMEM_B>>>(qhp, khp, vhp, amask, scop, attnp, attnh);

    // 3) depthwise conv (smem-staged, fp16)
    dwconv_k<<<dim3(SS / DW_POS, BB), 384>>>(hidh, dwk);

    // 4) pointwise: ks = dw @ pw^T + sep_bias
    hgemm<H_NT><<<dim3(AHSZ / 64, MROWS / MT, 1), 256, HG_SMEM>>>(
        dwh, nullptr,
        pwth, nullptr, nullptr, sepb, nullptr, nullptr,
        ks, nullptr, nullptr, nullptr, nullptr, nullptr,
        HIDC, HIDC, AHSZ, AHSZ);

    // 5) filter logits: (ks*q) @ Wak + bak
    hgemm_filt<<<dim3(1, MROWS / 128), 128>>>(ks, qf, wakh, bak, lg);

    // 6) tap softmax + windowed value conv (smem-staged)
    convout_k<<<dim3(SS / CO_POS, BB), 384>>>();

    // 7) fused mix: context = [attn@Wsl+bsl | conv@Wcl+bcl]
    hgemm<H_MIX><<<dim3(AHSZ / 64, MROWS / MT, 2), 256, HG_SMEM>>>(
        attnh, convh,
        wslh, wclh, nullptr, bsl, bcl, nullptr,
        outp, nullptr, nullptr, nullptr, nullptr, nullptr,
        AHSZ, AHSZ, AHSZ, HIDC);
}

// round 15
// speedup vs baseline: 1.0202x; 1.0202x over previous
#include <cuda_runtime.h>
#include <cuda_fp16.h>
#include <math.h>
#include <stdint.h>

// ---------------- problem constants ----------------
#define BB    4
#define SS    2048
#define HIDC  768
#define NH    6
#define HD    64
#define AHSZ  384
#define KW    9
#define MROWS (BB*SS)      // 8192
#define NZ    (BB*NH)      // 24
#define HK    (NH*KW)      // 54

// ---------------- scratch ----------------
__device__ __half g_hidden_h[MROWS*HIDC];
__device__ __half g_qh[MROWS*AHSZ];
__device__ __half g_kh[MROWS*AHSZ];
__device__ __half g_vh[MROWS*AHSZ];
__device__ float  g_q [MROWS*AHSZ];      // fp32 q for FILT elementwise
__device__ float  g_v [MROWS*AHSZ];      // fp32 v for convout
__device__ __half g_dwh[MROWS*HIDC];
__device__ float  g_ks[MROWS*AHSZ];
__device__ __half g_convh[MROWS*AHSZ];
__device__ float  g_logits[MROWS*HK];
__device__ __half g_attn_h[MROWS*AHSZ];
// fp16 weight copies
__device__ __half g_Wq_h[HIDC*AHSZ];
__device__ __half g_Wk_h[HIDC*AHSZ];
__device__ __half g_Wv_h[HIDC*AHSZ];
__device__ __half g_pwt_h[HIDC*AHSZ];    // pw transposed to [c][o]
__device__ __half g_Wsl_h[AHSZ*AHSZ];
__device__ __half g_Wcl_h[AHSZ*AHSZ];
__device__ __half g_Wak_h[AHSZ*64];      // padded 54 -> 64
// fallbacks
__device__ float g_attn_fb[MROWS*AHSZ];
__device__ float g_sco_fb [(size_t)NZ*SS*SS];

// ---------------- mma / ldmatrix / cp.async helpers ----------------
__device__ __forceinline__ void mma_f16(float* d, const unsigned* a, unsigned b0, unsigned b1) {
    asm volatile(
        "mma.sync.aligned.m16n8k16.row.col.f32.f16.f16.f32 "
        "{%0,%1,%2,%3}, {%4,%5,%6,%7}, {%8,%9}, {%0,%1,%2,%3};"
        : "+f"(d[0]), "+f"(d[1]), "+f"(d[2]), "+f"(d[3])
        : "r"(a[0]), "r"(a[1]), "r"(a[2]), "r"(a[3]), "r"(b0), "r"(b1));
}
__device__ __forceinline__ unsigned pack_f16(float lo, float hi) {
    unsigned r;
    asm("cvt.rn.f16x2.f32 %0, %1, %2;" : "=r"(r) : "f"(hi), "f"(lo));
    return r;
}
__device__ __forceinline__ void ldsm4(unsigned* r, unsigned addr) {
    asm volatile("ldmatrix.sync.aligned.m8n8.x4.shared.b16 {%0,%1,%2,%3}, [%4];"
        : "=r"(r[0]), "=r"(r[1]), "=r"(r[2]), "=r"(r[3]) : "r"(addr));
}
__device__ __forceinline__ void ldsm4t(unsigned* r, unsigned addr) {
    asm volatile("ldmatrix.sync.aligned.m8n8.x4.trans.shared.b16 {%0,%1,%2,%3}, [%4];"
        : "=r"(r[0]), "=r"(r[1]), "=r"(r[2]), "=r"(r[3]) : "r"(addr));
}
__device__ __forceinline__ unsigned s2u(const void* p) {
    return (unsigned)__cvta_generic_to_shared(p);
}
__device__ __forceinline__ void cpa16(unsigned dst, const void* src) {
    asm volatile("cp.async.ca.shared.global [%0], [%1], 16;" :: "r"(dst), "l"(src));
}
__device__ __forceinline__ void cpa_commit() { asm volatile("cp.async.commit_group;"); }
template <int N>
__device__ __forceinline__ void cpa_wait() { asm volatile("cp.async.wait_group %0;" :: "n"(N)); }

// ---------------- prep kernels ----------------
__global__ void __launch_bounds__(256) cvt_multi(
    const float4* s0, __half2* d0, int e0,
    const float4* s1, __half2* d1, int e1,
    const float4* s2, __half2* d2, int e2,
    const float4* s3, __half2* d3, int e3,
    const float4* s4, __half2* d4, int e4,
    const float4* s5, __half2* d5, int e5)
{
    const int i = blockIdx.x * 256 + threadIdx.x;
    const float4* s; __half2* d; int base;
    if      (i < e0) { s = s0; d = d0; base = 0;  }
    else if (i < e1) { s = s1; d = d1; base = e0; }
    else if (i < e2) { s = s2; d = d2; base = e1; }
    else if (i < e3) { s = s3; d = d3; base = e2; }
    else if (i < e4) { s = s4; d = d4; base = e3; }
    else if (i < e5) { s = s5; d = d5; base = e4; }
    else return;
    const int j = i - base;
    const float4 x = s[j];
    d[2 * j + 0] = __floats2half2_rn(x.x, x.y);
    d[2 * j + 1] = __floats2half2_rn(x.z, x.w);
}

__global__ void transpose_pw(const float* __restrict__ pw, __half* __restrict__ out)
{
    __shared__ float t[32][33];
    const int c0 = blockIdx.x * 32, o0 = blockIdx.y * 32;
    for (int i = threadIdx.y; i < 32; i += 8)
        t[i][threadIdx.x] = pw[(size_t)(o0 + i) * HIDC + c0 + threadIdx.x];
    __syncthreads();
    for (int i = threadIdx.y; i < 32; i += 8)
        out[(size_t)(c0 + i) * AHSZ + o0 + threadIdx.x] = __float2half(t[threadIdx.x][i]);
}

__global__ void pad_wak(const float* __restrict__ Wak, __half* __restrict__ out)
{
    const int r = blockIdx.x, t = threadIdx.x;  // 384 x 64
    out[r * 64 + t] = (t < HK) ? __float2half(Wak[r * HK + t]) : __half(0.f);
}

// =================== fp16 hgemm v4: 128x64x64, 256 thr, 8 warps (R11 layout, BK=64) ===================
// R8/R11-proven fragment layout (warp w owns m16 rows w*16..+15); BK doubled to 64
// so each warp runs 32 mma between syncs instead of 16 (halved sync cadence).
enum { H_QKV = 0, H_NT = 1, H_MIX = 3 };
#define A_P2 72   // halves pitch of A tile (64+8)
#define B_P  72   // halves pitch of B tile (64+8)
#define A_STAGE_B (128*A_P2*2)      // 18432 bytes per A stage
#define B_STAGE_B (64*B_P*2)        // 9216 bytes per B stage
#define HG_SMEM (2*A_STAGE_B + 2*B_STAGE_B)   // 55296 bytes

template <int MODE>
__global__ void __launch_bounds__(256) hgemm(
    const __half* __restrict__ Ah0, const __half* __restrict__ Ah1,
    const __half* __restrict__ B0, const __half* __restrict__ B1, const __half* __restrict__ B2,
    const float* __restrict__ b0p, const float* __restrict__ b1p, const float* __restrict__ b2p,
    float* C0f, float* C1f, float* C2f,
    __half* C0h, __half* C1h, __half* C2h,
    int Kdim, int lda, int ldw, int ldc)
{
    extern __shared__ char smc[];
    const unsigned sb = s2u(smc);
    const unsigned b_base = sb + 2 * A_STAGE_B;

    const int tid = threadIdx.x;
    const int w = tid >> 5, lane = tid & 31;
    const int lq = lane >> 2, lr = lane & 3;
    const int m0 = blockIdx.y * 128;
    const int n0 = blockIdx.x * 64;

    const __half* A = Ah0;
    const __half* B = B0;
    const float* bias = b0p;
    float* Cf = C0f;
    __half* Ch = C0h;
    if constexpr (MODE == H_QKV) {
        const int z = blockIdx.z;
        B    = (z == 0) ? B0 : ((z == 1) ? B1 : B2);
        bias = (z == 0) ? b0p : ((z == 1) ? b1p : b2p);
        Cf   = (z == 0) ? C0f : ((z == 1) ? C1f : C2f);
        Ch   = (z == 0) ? C0h : ((z == 1) ? C1h : C2h);
    }
    if constexpr (MODE == H_MIX) {
        const int z = blockIdx.z;
        A = z ? Ah1 : Ah0;
        B = z ? B1 : B0;
        bias = z ? b1p : b0p;
        Cf = C0f + z * AHSZ;
    }

    float c[8][4];
#pragma unroll
    for (int j = 0; j < 8; j++)
#pragma unroll
        for (int r = 0; r < 4; r++) c[j][r] = 0.f;

    // ldmatrix lane addresses (R8/R11 layout)
    const unsigned a_lane_b = sb +
        (unsigned)(((w * 16 + (lane & 15)) * A_P2 + (lane >> 4) * 8) * 2);
    const unsigned b_lane_b = b_base +
        (unsigned)((((lane & 7) + ((lane >> 3) & 1) * 8) * B_P + ((lane >> 3) >> 1) * 8) * 2);

    // staging (256 threads): A row tid>>1, half-row (tid&1)*32 -> 4 cpa16;
    //                        B row tid>>2, chunk (tid&3)*16 -> 2 cpa16
    const int ar = tid >> 1;
    const unsigned acb = (unsigned)(tid & 1) * 32u;
    const int br = tid >> 2, bcb = (tid & 3) * 16;

    const unsigned a_st = sb + (unsigned)((ar * A_P2 + (int)acb) * 2);
    const unsigned b_st = b_base + (unsigned)((br * B_P + bcb) * 2);

    const int NIT = Kdim / 64;
    {
        const __half* ap = &A[(size_t)(m0 + ar) * lda + acb];
#pragma unroll
        for (int u = 0; u < 4; u++) cpa16(a_st + u * 16, ap + u * 8);
        const __half* bp = &B[(size_t)br * ldw + n0 + bcb];
        cpa16(b_st, bp);
        cpa16(b_st + 16, bp + 8);
        cpa_commit();
    }

    for (int it = 0; it < NIT; it++) {
        if (it + 1 < NIT) {
            const int k0 = (it + 1) * 64;
            const unsigned s = (unsigned)((it + 1) & 1);
            const __half* ap = &A[(size_t)(m0 + ar) * lda + k0 + acb];
#pragma unroll
            for (int u = 0; u < 4; u++) cpa16(a_st + s * A_STAGE_B + u * 16, ap + u * 8);
            const __half* bp = &B[(size_t)(k0 + br) * ldw + n0 + bcb];
            cpa16(b_st + s * B_STAGE_B, bp);
            cpa16(b_st + s * B_STAGE_B + 16, bp + 8);
            cpa_commit();
            cpa_wait<1>();
        } else {
            cpa_wait<0>();
        }
        __syncthreads();

        const unsigned s = (unsigned)(it & 1);
        const unsigned a_lane = a_lane_b + s * A_STAGE_B;
        const unsigned b_lane = b_lane_b + s * B_STAGE_B;
#pragma unroll
        for (int kc = 0; kc < 4; kc++) {
            unsigned af[4];
            ldsm4(af, a_lane + (unsigned)(kc * 32));
#pragma unroll
            for (int nb = 0; nb < 4; nb++) {
                unsigned kb[4];
                ldsm4t(kb, b_lane + (unsigned)((kc * 16 * B_P + nb * 16) * 2));
                mma_f16(c[2 * nb],     af, kb[0], kb[1]);
                mma_f16(c[2 * nb + 1], af, kb[2], kb[3]);
            }
        }
        __syncthreads();
    }

    // ---- epilogue (R8/R11) ----
    const int rowA = m0 + w * 16 + lq;
#pragma unroll
    for (int j = 0; j < 8; j++) {
        const int n = n0 + j * 8 + 2 * lr;
        const float bj0 = bias[n], bj1 = bias[n + 1];
        const float v0 = c[j][0] + bj0, v1 = c[j][1] + bj1;
        const float v2 = c[j][2] + bj0, v3 = c[j][3] + bj1;
        if (Cf) {
            *reinterpret_cast<float2*>(&Cf[(size_t)rowA * ldc + n]) = make_float2(v0, v1);
            *reinterpret_cast<float2*>(&Cf[(size_t)(rowA + 8) * ldc + n]) = make_float2(v2, v3);
        }
        if constexpr (MODE == H_QKV) {
            *reinterpret_cast<unsigned*>(&Ch[(size_t)rowA * ldc + n]) = pack_f16(v0, v1);
            *reinterpret_cast<unsigned*>(&Ch[(size_t)(rowA + 8) * ldc + n]) = pack_f16(v2, v3);
        }
    }
}

// =================== FILT: (ks*q) @ Wak + bak (R11-proven 128-thr, 2 m-tiles/warp) ===================
#define AF_P 40
__global__ void __launch_bounds__(128) hgemm_filt(
    const float* __restrict__ Af0, const float* __restrict__ Af1,
    const __half* __restrict__ B0, const float* __restrict__ bias, float* __restrict__ Cf)
{
    __shared__ __half Ash[128 * AF_P];
    __shared__ __half Bsh[32 * B_P];

    const int tid = threadIdx.x;
    const int w = tid >> 5, lane = tid & 31;
    const int lq = lane >> 2, lr = lane & 3;
    const int m0 = blockIdx.y * 128;

    float c[2][8][4];
#pragma unroll
    for (int mi = 0; mi < 2; mi++)
#pragma unroll
        for (int j = 0; j < 8; j++)
#pragma unroll
            for (int r = 0; r < 4; r++) c[mi][j][r] = 0.f;

    unsigned a_lane[2];
#pragma unroll
    for (int mi = 0; mi < 2; mi++)
        a_lane[mi] = s2u(Ash) +
            (unsigned)(((w * 32 + mi * 16 + (lane & 15)) * AF_P + (lane >> 4) * 8) * 2);
    const unsigned b_lane = s2u(Bsh) +
        (unsigned)((((lane & 7) + ((lane >> 3) & 1) * 8) * B_P + ((lane >> 3) >> 1) * 8) * 2);

    const int ar = tid;
    const int br = tid >> 2, bcb = (tid & 3) * 16;

    for (int k0 = 0; k0 < AHSZ; k0 += 32) {
        {
            const float* pa = &Af0[(size_t)(m0 + ar) * AHSZ + k0];
            const float* pb = &Af1[(size_t)(m0 + ar) * AHSZ + k0];
            __half2* dst = reinterpret_cast<__half2*>(&Ash[ar * AF_P]);
#pragma unroll
            for (int u = 0; u < 8; u++) {
                const float4 xa = *reinterpret_cast<const float4*>(pa + u * 4);
                const float4 xb = *reinterpret_cast<const float4*>(pb + u * 4);
                dst[2 * u + 0] = __floats2half2_rn(xa.x * xb.x, xa.y * xb.y);
                dst[2 * u + 1] = __floats2half2_rn(xa.z * xb.z, xa.w * xb.w);
            }
        }
        {
            const __half* bp = &B0[(size_t)(k0 + br) * 64 + bcb];
            *reinterpret_cast<uint4*>(&Bsh[br * B_P + bcb]) =
                *reinterpret_cast<const uint4*>(bp);
            *reinterpret_cast<uint4*>(&Bsh[br * B_P + bcb + 8]) =
                *reinterpret_cast<const uint4*>(bp + 8);
        }
        __syncthreads();

#pragma unroll
        for (int kc = 0; kc < 2; kc++) {
            unsigned af[2][4];
#pragma unroll
            for (int mi = 0; mi < 2; mi++)
                ldsm4(af[mi], a_lane[mi] + (unsigned)(kc * 32));
#pragma unroll
            for (int nb = 0; nb < 4; nb++) {
                unsigned kb[4];
                ldsm4t(kb, b_lane + (unsigned)((kc * 16 * B_P + nb * 16) * 2));
#pragma unroll
                for (int mi = 0; mi < 2; mi++) {
                    mma_f16(c[mi][2 * nb],     af[mi], kb[0], kb[1]);
                    mma_f16(c[mi][2 * nb + 1], af[mi], kb[2], kb[3]);
                }
            }
        }
        __syncthreads();
    }

#pragma unroll
    for (int mi = 0; mi < 2; mi++) {
        const int rowA = m0 + w * 32 + mi * 16 + lq;
#pragma unroll
        for (int j = 0; j < 8; j++) {
            const int n = j * 8 + 2 * lr;
            if (n < HK) {
                const float bj0 = bias[n], bj1 = bias[n + 1];
                *reinterpret_cast<float2*>(&Cf[(size_t)rowA * HK + n]) =
                    make_float2(c[mi][j][0] + bj0, c[mi][j][1] + bj1);
                *reinterpret_cast<float2*>(&Cf[(size_t)(rowA + 8) * HK + n]) =
                    make_float2(c[mi][j][2] + bj0, c[mi][j][3] + bj1);
            }
        }
    }
}

// =================== fused flash attention v4 (R11 proven) ===================
#define FQ_P 72
#define KV_STAGE (64*FQ_P*2)
#define FA_SMEM_B (4*KV_STAGE + SS*4)

__global__ void __launch_bounds__(128, 2) fattn_k(
    const __half* __restrict__ qh, const __half* __restrict__ kh, const __half* __restrict__ vh,
    const float* __restrict__ amask, float* __restrict__ scores,
    float* __restrict__ attn, __half* __restrict__ attnh)
{
    extern __shared__ char smc[];
    __half* Qh = (__half*)smc;
    __half* Ksh = (__half*)smc;
    __half* Vsh = (__half*)(smc + 2 * KV_STAGE);
    float* msk = (float*)(smc + 4 * KV_STAGE);

    const int tid  = threadIdx.x;
    const int w    = tid >> 5, lane = tid & 31;
    const int lq   = lane >> 2, lr = lane & 3;
    const int m0   = blockIdx.x * 128;
    const int z    = blockIdx.y, b = z / NH, h = z % NH;

    {
        const float4* s4 = reinterpret_cast<const float4*>(amask + (size_t)b * SS);
        float4* d4 = reinterpret_cast<float4*>(msk);
        for (int i = tid; i < SS / 4; i += 128) d4[i] = s4[i];
    }
    {
        const __half* qp = qh + ((size_t)(b * SS + m0 + tid)) * AHSZ + h * HD;
        uint4* dst = reinterpret_cast<uint4*>(&Qh[tid * FQ_P]);
#pragma unroll
        for (int u = 0; u < 8; u++) dst[u] = *reinterpret_cast<const uint4*>(qp + u * 8);
    }
    __syncthreads();

    unsigned Qa[2][4][4];
#pragma unroll
    for (int mi = 0; mi < 2; mi++) {
        const unsigned q_lane = s2u(Qh) +
            (unsigned)(((w * 32 + mi * 16 + (lane & 15)) * FQ_P + (lane >> 4) * 8) * 2);
#pragma unroll
        for (int kc = 0; kc < 4; kc++) ldsm4(Qa[mi][kc], q_lane + (unsigned)(kc * 32));
    }
    __syncthreads();

    float o[2][8][4];
#pragma unroll
    for (int mi = 0; mi < 2; mi++)
#pragma unroll
        for (int d = 0; d < 8; d++)
#pragma unroll
            for (int r = 0; r < 4; r++) o[mi][d][r] = 0.f;
    float lacc[2][2] = {{0.f, 0.f}, {0.f, 0.f}};

    const __half* kbase = kh + (size_t)b * SS * AHSZ + h * HD;
    const __half* vbase = vh + (size_t)b * SS * AHSZ + h * HD;
    float* sco = scores + (size_t)z * SS * SS;

    const unsigned k_lane_b = s2u(Ksh) +
        (unsigned)((((lane & 15)) * FQ_P + (lane >> 4) * 8) * 2);
    const unsigned v_lane_b = s2u(Vsh) +
        (unsigned)((((lane & 7) + ((lane >> 3) & 1) * 8) * FQ_P + ((lane >> 3) >> 1) * 8) * 2);

    const int sr = tid >> 1;
    const unsigned scb = (unsigned)(tid & 1) * 64u;
    const unsigned k_st = s2u(Ksh) + (unsigned)(sr * FQ_P * 2) + scb;
    const unsigned v_st = s2u(Vsh) + (unsigned)(sr * FQ_P * 2) + scb;
    const int sco_h = (tid & 1) * 32;

    {
        const __half* kp = kbase + (size_t)sr * AHSZ + sco_h;
        const __half* vp = vbase + (size_t)sr * AHSZ + sco_h;
#pragma unroll
        for (int u = 0; u < 4; u++) {
            cpa16(k_st + u * 16, kp + u * 8);
            cpa16(v_st + u * 16, vp + u * 8);
        }
        cpa_commit();
    }

    for (int kt = 0; kt < 32; kt++) {
        const int n0 = kt * 64;
        if (kt < 31) {
            const unsigned s = (unsigned)((kt + 1) & 1) * KV_STAGE;
            const __half* kp = kbase + (size_t)(n0 + 64 + sr) * AHSZ + sco_h;
            const __half* vp = vbase + (size_t)(n0 + 64 + sr) * AHSZ + sco_h;
#pragma unroll
            for (int u = 0; u < 4; u++) {
                cpa16(k_st + s + u * 16, kp + u * 8);
                cpa16(v_st + s + u * 16, vp + u * 8);
            }
            cpa_commit();
            cpa_wait<1>();
        } else {
            cpa_wait<0>();
        }
        __syncthreads();

        const unsigned s = (unsigned)(kt & 1) * KV_STAGE;
        const unsigned k_lane = k_lane_b + s;
        const unsigned v_lane = v_lane_b + s;

#pragma unroll
        for (int kg = 0; kg < 4; kg++) {
            float c[2][2][4];
#pragma unroll
            for (int mi = 0; mi < 2; mi++)
#pragma unroll
                for (int jj = 0; jj < 2; jj++)
#pragma unroll
                    for (int r = 0; r < 4; r++) c[mi][jj][r] = 0.f;
#pragma unroll
            for (int kc = 0; kc < 4; kc++) {
                unsigned kb[4];
                ldsm4(kb, k_lane + (unsigned)((kg * 16 * FQ_P + kc * 16) * 2));
#pragma unroll
                for (int mi = 0; mi < 2; mi++) {
                    mma_f16(c[mi][0], Qa[mi][kc], kb[0], kb[2]);
                    mma_f16(c[mi][1], Qa[mi][kc], kb[1], kb[3]);
                }
            }

            unsigned pa[2][4];
#pragma unroll
            for (int mi = 0; mi < 2; mi++) {
                const int row0 = w * 32 + mi * 16 + lq;
#pragma unroll
                for (int jj = 0; jj < 2; jj++) {
                    const int colL = kg * 16 + jj * 8 + 2 * lr;
                    const float mk0 = msk[n0 + colL], mk1 = msk[n0 + colL + 1];
                    const float s0 = c[mi][jj][0] * 0.125f + mk0;
                    const float s1 = c[mi][jj][1] * 0.125f + mk1;
                    const float s2 = c[mi][jj][2] * 0.125f + mk0;
                    const float s3 = c[mi][jj][3] * 0.125f + mk1;
                    *reinterpret_cast<float2*>(&sco[(size_t)(m0 + row0) * SS + n0 + colL]) =
                        make_float2(s0, s1);
                    *reinterpret_cast<float2*>(&sco[(size_t)(m0 + row0 + 8) * SS + n0 + colL]) =
                        make_float2(s2, s3);
                    const float p0 = __expf(s0), p1 = __expf(s1);
                    const float p2 = __expf(s2), p3 = __expf(s3);
                    lacc[mi][0] += p0 + p1;
                    lacc[mi][1] += p2 + p3;
                    pa[mi][jj * 2 + 0] = pack_f16(p0, p1);
                    pa[mi][jj * 2 + 1] = pack_f16(p2, p3);
                }
            }

#pragma unroll
            for (int dp = 0; dp < 4; dp++) {
                unsigned vb[4];
                ldsm4t(vb, v_lane + (unsigned)((kg * 16 * FQ_P + dp * 16) * 2));
#pragma unroll
                for (int mi = 0; mi < 2; mi++) {
                    mma_f16(o[mi][2 * dp],     pa[mi], vb[0], vb[1]);
                    mma_f16(o[mi][2 * dp + 1], pa[mi], vb[2], vb[3]);
                }
            }
        }
        __syncthreads();
    }

#pragma unroll
    for (int mi = 0; mi < 2; mi++) {
        float l0 = lacc[mi][0], l1 = lacc[mi][1];
        l0 += __shfl_xor_sync(0xFFFFFFFFu, l0, 1);
        l0 += __shfl_xor_sync(0xFFFFFFFFu, l0, 2);
        l1 += __shfl_xor_sync(0xFFFFFFFFu, l1, 1);
        l1 += __shfl_xor_sync(0xFFFFFFFFu, l1, 2);
        const float inv0 = 1.f / l0, inv1 = 1.f / l1;
        const int row0 = w * 32 + mi * 16 + lq;
#pragma unroll
        for (int d = 0; d < 8; d++) {
            const int col = h * HD + d * 8 + 2 * lr;
            const size_t r0 = ((size_t)(b * SS + m0 + row0)) * AHSZ + col;
            const size_t r1 = ((size_t)(b * SS + m0 + row0 + 8)) * AHSZ + col;
            const float v0 = o[mi][d][0] * inv0, v1 = o[mi][d][1] * inv0;
            const float v2 = o[mi][d][2] * inv1, v3 = o[mi][d][3] * inv1;
            *reinterpret_cast<float2*>(&attn[r0]) = make_float2(v0, v1);
            *reinterpret_cast<float2*>(&attn[r1]) = make_float2(v2, v3);
            *reinterpret_cast<unsigned*>(&attnh[r0]) = pack_f16(v0, v1);
            *reinterpret_cast<unsigned*>(&attnh[r1]) = pack_f16(v2, v3);
        }
    }
}

// ---------------- depthwise conv: smem-staged ----------------
#define DW_POS 16
__global__ void __launch_bounds__(384) dwconv_k(const __half* __restrict__ xh,
                                                const float* __restrict__ dwk)
{
    __shared__ __half hsm[(DW_POS + 8) * HIDC];
    const int s0 = blockIdx.x * DW_POS;
    const int b  = blockIdx.y;
    const int tid = threadIdx.x;

    for (int idx = tid; idx < (DW_POS + 8) * (HIDC / 8); idx += 384) {
        const int row = idx / (HIDC / 8);
        const int cb  = (idx % (HIDC / 8)) * 8;
        const int sp  = s0 - 4 + row;
        uint4 val = make_uint4(0, 0, 0, 0);
        if (sp >= 0 && sp < SS)
            val = *reinterpret_cast<const uint4*>(&xh[((size_t)b * SS + sp) * HIDC + cb]);
        *reinterpret_cast<uint4*>(&hsm[row * HIDC + cb]) = val;
    }
    __syncthreads();

    const int c0 = tid * 2;
    float kw0[KW], kw1[KW];
#pragma unroll
    for (int tp = 0; tp < KW; tp++) {
        kw0[tp] = dwk[c0 * KW + tp];
        kw1[tp] = dwk[(c0 + 1) * KW + tp];
    }

    for (int ls = 0; ls < DW_POS; ls++) {
        float a0 = 0.f, a1 = 0.f;
#pragma unroll
        for (int tp = 0; tp < KW; tp++) {
            const float2 xv = __half22float2(
                *reinterpret_cast<const __half2*>(&hsm[(ls + tp) * HIDC + c0]));
            a0 += xv.x * kw0[tp];
            a1 += xv.y * kw1[tp];
        }
        *reinterpret_cast<__half2*>(&g_dwh[((size_t)b * SS + s0 + ls) * HIDC + c0]) =
            __floats2half2_rn(a0, a1);
    }
}

// ---------------- tap softmax + windowed value conv: smem-staged ----------------
#define CO_POS 16
__global__ void __launch_bounds__(384) convout_k()
{
    __shared__ float vsm[(CO_POS + 8) * AHSZ];
    __shared__ float filt[CO_POS][HK + 2];
    const int s0 = blockIdx.x * CO_POS;
    const int b  = blockIdx.y;
    const int tid = threadIdx.x;

    for (int idx = tid; idx < (CO_POS + 8) * (AHSZ / 4); idx += 384) {
        const int row = idx / (AHSZ / 4);
        const int cb  = (idx % (AHSZ / 4)) * 4;
        const int sp  = s0 - 4 + row;
        float4 val = make_float4(0.f, 0.f, 0.f, 0.f);
        if (sp >= 0 && sp < SS)
            val = *reinterpret_cast<const float4*>(&g_v[((size_t)b * SS + sp) * AHSZ + cb]);
        *reinterpret_cast<float4*>(&vsm[row * AHSZ + cb]) = val;
    }

    if (tid < CO_POS * NH) {
        const int ls = tid % CO_POS, h = tid / CO_POS;
        const size_t mrow = (size_t)(b * SS + s0 + ls) * HK + h * KW;
        float lg[KW];
        float mx = -1e30f;
#pragma unroll
        for (int i = 0; i < KW; i++) {
            lg[i] = g_logits[mrow + i];
            mx = fmaxf(mx, lg[i]);
        }
        float sum = 0.f;
#pragma unroll
        for (int i = 0; i < KW; i++) { lg[i] = __expf(lg[i] - mx); sum += lg[i]; }
        const float is = 1.f / sum;
#pragma unroll
        for (int i = 0; i < KW; i++) filt[ls][h * KW + i] = lg[i] * is;
    }
    __syncthreads();

    const int c = tid;
    const int hb = (c >> 6) * KW;
    for (int ls = 0; ls < CO_POS; ls++) {
        float acc = 0.f;
#pragma unroll
        for (int tp = 0; tp < KW; tp++)
            acc += vsm[(ls + tp) * AHSZ + c] * filt[ls][hb + tp];
        g_convh[((size_t)(b * SS + s0 + ls)) * AHSZ + c] = __float2half(acc);
    }
}

// ---------------- launch (serial, default stream) ----------------
extern "C" void kernel_launch(void* const* d_in, const int* in_sizes, int n_in,
                              void* d_out, int out_size)
{
    const float* hidden = (const float*)d_in[0];
    const float* amask  = (const float*)d_in[1];
    const float* Wq = (const float*)d_in[2];  const float* bq = (const float*)d_in[3];
    const float* Wk = (const float*)d_in[4];  const float* bk = (const float*)d_in[5];
    const float* Wv = (const float*)d_in[6];  const float* bv = (const float*)d_in[7];
    const float* dwk = (const float*)d_in[8];
    const float* pw  = (const float*)d_in[9]; const float* sepb = (const float*)d_in[10];
    const float* Wak = (const float*)d_in[11]; const float* bak = (const float*)d_in[12];
    const float* Wsl = (const float*)d_in[13]; const float* bsl = (const float*)d_in[14];
    const float* Wcl = (const float*)d_in[15]; const float* bcl = (const float*)d_in[16];

    __half *hidh, *qhp, *khp, *vhp, *dwh, *convh, *attnh;
    __half *wqh, *wkh, *wvh, *pwth, *wslh, *wclh, *wakh;
    float *qf, *vf, *ks, *lg, *attn_fb, *sco_fb;
    cudaGetSymbolAddress((void**)&hidh,  g_hidden_h);
    cudaGetSymbolAddress((void**)&qhp,   g_qh);
    cudaGetSymbolAddress((void**)&khp,   g_kh);
    cudaGetSymbolAddress((void**)&vhp,   g_vh);
    cudaGetSymbolAddress((void**)&qf,    g_q);
    cudaGetSymbolAddress((void**)&vf,    g_v);
    cudaGetSymbolAddress((void**)&dwh,   g_dwh);
    cudaGetSymbolAddress((void**)&ks,    g_ks);
    cudaGetSymbolAddress((void**)&convh, g_convh);
    cudaGetSymbolAddress((void**)&lg,    g_logits);
    cudaGetSymbolAddress((void**)&attnh, g_attn_h);
    cudaGetSymbolAddress((void**)&wqh,   g_Wq_h);
    cudaGetSymbolAddress((void**)&wkh,   g_Wk_h);
    cudaGetSymbolAddress((void**)&wvh,   g_Wv_h);
    cudaGetSymbolAddress((void**)&pwth,  g_pwt_h);
    cudaGetSymbolAddress((void**)&wslh,  g_Wsl_h);
    cudaGetSymbolAddress((void**)&wclh,  g_Wcl_h);
    cudaGetSymbolAddress((void**)&wakh,  g_Wak_h);
    cudaGetSymbolAddress((void**)&attn_fb, g_attn_fb);
    cudaGetSymbolAddress((void**)&sco_fb,  g_sco_fb);

    float* outp = (float*)d_out;
    const size_t CTX_SZ = (size_t)MROWS * HIDC;
    const size_t ATT_OFF = CTX_SZ;
    const size_t ATT_SZ  = (size_t)MROWS * AHSZ;
    const size_t SCO_OFF = ATT_OFF + ATT_SZ;
    const size_t SCO_SZ  = (size_t)NZ * SS * SS;
    float* attnp = ((size_t)out_size >= ATT_OFF + ATT_SZ) ? outp + ATT_OFF : attn_fb;
    float* scop  = ((size_t)out_size >= SCO_OFF + SCO_SZ) ? outp + SCO_OFF : sco_fb;

    // ---- prep: fused conversions + pw transpose + wak pad ----
    {
        const int n0 = MROWS * HIDC / 4;
        const int nw = HIDC * AHSZ / 4;
        const int nm = AHSZ * AHSZ / 4;
        const int e0 = n0, e1 = e0 + nw, e2 = e1 + nw, e3 = e2 + nw;
        const int e4 = e3 + nm, e5 = e4 + nm;
        cvt_multi<<<(e5 + 255) / 256, 256>>>(
            (const float4*)hidden, (__half2*)hidh, e0,
            (const float4*)Wq,  (__half2*)wqh,  e1,
            (const float4*)Wk,  (__half2*)wkh,  e2,
            (const float4*)Wv,  (__half2*)wvh,  e3,
            (const float4*)Wsl, (__half2*)wslh, e4,
            (const float4*)Wcl, (__half2*)wclh, e5);
    }
    transpose_pw<<<dim3(HIDC / 32, AHSZ / 32), dim3(32, 8)>>>(pw, pwth);
    pad_wak<<<AHSZ, 64>>>(Wak, wakh);

    // smem attrs for dynamic-smem kernels
    cudaFuncSetAttribute(hgemm<H_QKV>, cudaFuncAttributeMaxDynamicSharedMemorySize, HG_SMEM);
    cudaFuncSetAttribute(hgemm<H_NT>,  cudaFuncAttributeMaxDynamicSharedMemorySize, HG_SMEM);
    cudaFuncSetAttribute(hgemm<H_MIX>, cudaFuncAttributeMaxDynamicSharedMemorySize, HG_SMEM);
    cudaFuncSetAttribute(fattn_k, cudaFuncAttributeMaxDynamicSharedMemorySize, FA_SMEM_B);

    // 1) fused QKV (fp16, BK=64 double-buffered)
    hgemm<H_QKV><<<dim3(AHSZ / 64, MROWS / 128, 3), 256, HG_SMEM>>>(
        hidh, nullptr,
        wqh, wkh, wvh, bq, bk, bv,
        qf, nullptr, vf, qhp, khp, vhp,
        HIDC, HIDC, AHSZ, AHSZ);

    // 2) fused attention v4
    fattn_k<<<dim3(SS / 128, NZ), 128, FA_SMEM_B>>>(qhp, khp, vhp, amask, scop, attnp, attnh);

    // 3) depthwise conv (smem-staged, fp16)
    dwconv_k<<<dim3(SS / DW_POS, BB), 384>>>(hidh, dwk);

    // 4) pointwise: ks = dw @ pw^T + sep_bias
    hgemm<H_NT><<<dim3(AHSZ / 64, MROWS / 128, 1), 256, HG_SMEM>>>(
        dwh, nullptr,
        pwth, nullptr, nullptr, sepb, nullptr, nullptr,
        ks, nullptr, nullptr, nullptr, nullptr, nullptr,
        HIDC, HIDC, AHSZ, AHSZ);

    // 5) filter logits: (ks*q) @ Wak + bak
    hgemm_filt<<<dim3(1, MROWS / 128), 128>>>(ks, qf, wakh, bak, lg);

    // 6) tap softmax + windowed value conv (smem-staged)
    convout_k<<<dim3(SS / CO_POS, BB), 384>>>();

    // 7) fused mix: context = [attn@Wsl+bsl | conv@Wcl+bcl]
    hgemm<H_MIX><<<dim3(AHSZ / 64, MROWS / 128, 2), 256, HG_SMEM>>>(
        attnh, convh,
        wslh, wclh, nullptr, bsl, bcl, nullptr,
        outp, nullptr, nullptr, nullptr, nullptr, nullptr,
        AHSZ, AHSZ, AHSZ, HIDC);
}

// round 16
// speedup vs baseline: 1.0711x; 1.0499x over previous
#include <cuda_runtime.h>
#include <cuda_fp16.h>
#include <math.h>
#include <stdint.h>

// ---------------- problem constants ----------------
#define BB    4
#define SS    2048
#define HIDC  768
#define NH    6
#define HD    64
#define AHSZ  384
#define KW    9
#define MROWS (BB*SS)      // 8192
#define NZ    (BB*NH)      // 24
#define HK    (NH*KW)      // 54

// ---------------- scratch ----------------
__device__ __half g_hidden_h[MROWS*HIDC];
__device__ __half g_qh[MROWS*AHSZ];
__device__ __half g_kh[MROWS*AHSZ];
__device__ __half g_vh[MROWS*AHSZ];
__device__ __half g_dwh[MROWS*HIDC];
__device__ __half g_ksh[MROWS*AHSZ];     // fp16 ks (pointwise output)
__device__ __half g_convh[MROWS*AHSZ];
__device__ float  g_logits[MROWS*HK];
__device__ __half g_attn_h[MROWS*AHSZ];
// fp16 weight copies
__device__ __half g_Wq_h[HIDC*AHSZ];
__device__ __half g_Wk_h[HIDC*AHSZ];
__device__ __half g_Wv_h[HIDC*AHSZ];
__device__ __half g_pwt_h[HIDC*AHSZ];    // pw transposed to [c][o]
__device__ __half g_Wsl_h[AHSZ*AHSZ];
__device__ __half g_Wcl_h[AHSZ*AHSZ];
__device__ __half g_Wak_h[AHSZ*64];      // padded 54 -> 64
// fallbacks
__device__ float g_attn_fb[MROWS*AHSZ];
__device__ float g_sco_fb [(size_t)NZ*SS*SS];

// ---------------- mma / ldmatrix / cp.async helpers ----------------
__device__ __forceinline__ void mma_f16(float* d, const unsigned* a, unsigned b0, unsigned b1) {
    asm volatile(
        "mma.sync.aligned.m16n8k16.row.col.f32.f16.f16.f32 "
        "{%0,%1,%2,%3}, {%4,%5,%6,%7}, {%8,%9}, {%0,%1,%2,%3};"
        : "+f"(d[0]), "+f"(d[1]), "+f"(d[2]), "+f"(d[3])
        : "r"(a[0]), "r"(a[1]), "r"(a[2]), "r"(a[3]), "r"(b0), "r"(b1));
}
__device__ __forceinline__ unsigned pack_f16(float lo, float hi) {
    unsigned r;
    asm("cvt.rn.f16x2.f32 %0, %1, %2;" : "=r"(r) : "f"(hi), "f"(lo));
    return r;
}
__device__ __forceinline__ void ldsm4(unsigned* r, unsigned addr) {
    asm volatile("ldmatrix.sync.aligned.m8n8.x4.shared.b16 {%0,%1,%2,%3}, [%4];"
        : "=r"(r[0]), "=r"(r[1]), "=r"(r[2]), "=r"(r[3]) : "r"(addr));
}
__device__ __forceinline__ void ldsm4t(unsigned* r, unsigned addr) {
    asm volatile("ldmatrix.sync.aligned.m8n8.x4.trans.shared.b16 {%0,%1,%2,%3}, [%4];"
        : "=r"(r[0]), "=r"(r[1]), "=r"(r[2]), "=r"(r[3]) : "r"(addr));
}
__device__ __forceinline__ unsigned s2u(const void* p) {
    return (unsigned)__cvta_generic_to_shared(p);
}
__device__ __forceinline__ void cpa16(unsigned dst, const void* src) {
    asm volatile("cp.async.ca.shared.global [%0], [%1], 16;" :: "r"(dst), "l"(src));
}
__device__ __forceinline__ void cpa_commit() { asm volatile("cp.async.commit_group;"); }
template <int N>
__device__ __forceinline__ void cpa_wait() { asm volatile("cp.async.wait_group %0;" :: "n"(N)); }

// ---------------- prep kernels ----------------
__global__ void __launch_bounds__(256) cvt_multi(
    const float4* s0, __half2* d0, int e0,
    const float4* s1, __half2* d1, int e1,
    const float4* s2, __half2* d2, int e2,
    const float4* s3, __half2* d3, int e3,
    const float4* s4, __half2* d4, int e4,
    const float4* s5, __half2* d5, int e5)
{
    const int i = blockIdx.x * 256 + threadIdx.x;
    const float4* s; __half2* d; int base;
    if      (i < e0) { s = s0; d = d0; base = 0;  }
    else if (i < e1) { s = s1; d = d1; base = e0; }
    else if (i < e2) { s = s2; d = d2; base = e1; }
    else if (i < e3) { s = s3; d = d3; base = e2; }
    else if (i < e4) { s = s4; d = d4; base = e3; }
    else if (i < e5) { s = s5; d = d5; base = e4; }
    else return;
    const int j = i - base;
    const float4 x = s[j];
    d[2 * j + 0] = __floats2half2_rn(x.x, x.y);
    d[2 * j + 1] = __floats2half2_rn(x.z, x.w);
}

__global__ void transpose_pw(const float* __restrict__ pw, __half* __restrict__ out)
{
    __shared__ float t[32][33];
    const int c0 = blockIdx.x * 32, o0 = blockIdx.y * 32;
    for (int i = threadIdx.y; i < 32; i += 8)
        t[i][threadIdx.x] = pw[(size_t)(o0 + i) * HIDC + c0 + threadIdx.x];
    __syncthreads();
    for (int i = threadIdx.y; i < 32; i += 8)
        out[(size_t)(c0 + i) * AHSZ + o0 + threadIdx.x] = __float2half(t[threadIdx.x][i]);
}

__global__ void pad_wak(const float* __restrict__ Wak, __half* __restrict__ out)
{
    const int r = blockIdx.x, t = threadIdx.x;  // 384 x 64
    out[r * 64 + t] = (t < HK) ? __float2half(Wak[r * HK + t]) : __half(0.f);
}

// =================== fp16 hgemm (R8/R11-proven): 128x64x32, 256 thr, static smem ===================
enum { H_QKV = 0, H_NT = 1, H_MIX = 3 };
#define A_P 40   // halves pitch of A tile (32+8)
#define B_P 72   // halves pitch of B tile (64+8)

template <int MODE>
__global__ void __launch_bounds__(256) hgemm(
    const __half* __restrict__ Ah0, const __half* __restrict__ Ah1,
    const __half* __restrict__ B0, const __half* __restrict__ B1, const __half* __restrict__ B2,
    const float* __restrict__ b0p, const float* __restrict__ b1p, const float* __restrict__ b2p,
    float* C0f, float* C1f, float* C2f,
    __half* C0h, __half* C1h, __half* C2h,
    int Kdim, int lda, int ldw, int ldc)
{
    __shared__ __half Ash[2][128 * A_P];
    __shared__ __half Bsh[2][32 * B_P];

    const int tid = threadIdx.x;
    const int w = tid >> 5, lane = tid & 31;
    const int lq = lane >> 2, lr = lane & 3;
    const int m0 = blockIdx.y * 128;
    const int n0 = blockIdx.x * 64;

    const __half* A = Ah0;
    const __half* B = B0;
    const float* bias = b0p;
    float* Cf = C0f;
    __half* Ch = C0h;
    if constexpr (MODE == H_QKV) {
        const int z = blockIdx.z;
        B    = (z == 0) ? B0 : ((z == 1) ? B1 : B2);
        bias = (z == 0) ? b0p : ((z == 1) ? b1p : b2p);
        Cf   = (z == 0) ? C0f : ((z == 1) ? C1f : C2f);
        Ch   = (z == 0) ? C0h : ((z == 1) ? C1h : C2h);
    }
    if constexpr (MODE == H_MIX) {
        const int z = blockIdx.z;
        A = z ? Ah1 : Ah0;
        B = z ? B1 : B0;
        bias = z ? b1p : b0p;
        Cf = C0f + z * AHSZ;
        Ch = nullptr;
    }

    float c[8][4];
#pragma unroll
    for (int j = 0; j < 8; j++)
#pragma unroll
        for (int r = 0; r < 4; r++) c[j][r] = 0.f;

    const unsigned a_lane_b = s2u(Ash) +
        (unsigned)(((w * 16 + (lane & 15)) * A_P + (lane >> 4) * 8) * 2);
    const unsigned b_lane_b = s2u(Bsh) +
        (unsigned)((((lane & 7) + ((lane >> 3) & 1) * 8) * B_P + ((lane >> 3) >> 1) * 8) * 2);

    const int ar = tid >> 1, acb = (tid & 1) * 16;
    const int br = tid >> 3, bcb = (tid & 7) * 8;

    const unsigned a_st = s2u(Ash) + (unsigned)((ar * A_P + acb) * 2);
    const unsigned b_st = s2u(Bsh) + (unsigned)((br * B_P + bcb) * 2);
    const unsigned A_STAGE = 128 * A_P * 2;
    const unsigned B_STAGE = 32 * B_P * 2;

    const int NIT = Kdim / 32;
    {
        const __half* ap = &A[(size_t)(m0 + ar) * lda + acb];
        cpa16(a_st, ap);
        cpa16(a_st + 16, ap + 8);
        cpa16(b_st, &B[(size_t)br * ldw + n0 + bcb]);
        cpa_commit();
    }

    for (int it = 0; it < NIT; it++) {
        if (it + 1 < NIT) {
            const int k0 = (it + 1) * 32;
            const unsigned s = (unsigned)((it + 1) & 1);
            const __half* ap = &A[(size_t)(m0 + ar) * lda + k0 + acb];
            cpa16(a_st + s * A_STAGE, ap);
            cpa16(a_st + s * A_STAGE + 16, ap + 8);
            cpa16(b_st + s * B_STAGE, &B[(size_t)(k0 + br) * ldw + n0 + bcb]);
            cpa_commit();
            cpa_wait<1>();
        } else {
            cpa_wait<0>();
        }
        __syncthreads();

        const unsigned s = (unsigned)(it & 1);
        const unsigned a_lane = a_lane_b + s * A_STAGE;
        const unsigned b_lane = b_lane_b + s * B_STAGE;
#pragma unroll
        for (int kc = 0; kc < 2; kc++) {
            unsigned af[4];
            ldsm4(af, a_lane + (unsigned)(kc * 32));
#pragma unroll
            for (int nb = 0; nb < 4; nb++) {
                unsigned kb[4];
                ldsm4t(kb, b_lane + (unsigned)((kc * 16 * B_P + nb * 16) * 2));
                mma_f16(c[2 * nb],     af, kb[0], kb[1]);
                mma_f16(c[2 * nb + 1], af, kb[2], kb[3]);
            }
        }
        __syncthreads();
    }

    // ---- epilogue: fp32 and/or fp16 stores ----
    const int rowA = m0 + w * 16 + lq;
#pragma unroll
    for (int j = 0; j < 8; j++) {
        const int n = n0 + j * 8 + 2 * lr;
        const float bj0 = bias[n], bj1 = bias[n + 1];
        const float v0 = c[j][0] + bj0, v1 = c[j][1] + bj1;
        const float v2 = c[j][2] + bj0, v3 = c[j][3] + bj1;
        if (Cf) {
            *reinterpret_cast<float2*>(&Cf[(size_t)rowA * ldc + n]) = make_float2(v0, v1);
            *reinterpret_cast<float2*>(&Cf[(size_t)(rowA + 8) * ldc + n]) = make_float2(v2, v3);
        }
        if (Ch) {
            *reinterpret_cast<unsigned*>(&Ch[(size_t)rowA * ldc + n]) = pack_f16(v0, v1);
            *reinterpret_cast<unsigned*>(&Ch[(size_t)(rowA + 8) * ldc + n]) = pack_f16(v2, v3);
        }
    }
}

// =================== FILT: (ksh*qh) @ Wak + bak (fp16 inputs, R11 shape) ===================
__global__ void __launch_bounds__(128) hgemm_filt(
    const __half* __restrict__ Ah0, const __half* __restrict__ Ah1,
    const __half* __restrict__ B0, const float* __restrict__ bias, float* __restrict__ Cf)
{
    __shared__ __half Ash[128 * A_P];
    __shared__ __half Bsh[32 * B_P];

    const int tid = threadIdx.x;
    const int w = tid >> 5, lane = tid & 31;
    const int lq = lane >> 2, lr = lane & 3;
    const int m0 = blockIdx.y * 128;

    float c[2][8][4];
#pragma unroll
    for (int mi = 0; mi < 2; mi++)
#pragma unroll
        for (int j = 0; j < 8; j++)
#pragma unroll
            for (int r = 0; r < 4; r++) c[mi][j][r] = 0.f;

    unsigned a_lane[2];
#pragma unroll
    for (int mi = 0; mi < 2; mi++)
        a_lane[mi] = s2u(Ash) +
            (unsigned)(((w * 32 + mi * 16 + (lane & 15)) * A_P + (lane >> 4) * 8) * 2);
    const unsigned b_lane = s2u(Bsh) +
        (unsigned)((((lane & 7) + ((lane >> 3) & 1) * 8) * B_P + ((lane >> 3) >> 1) * 8) * 2);

    const int ar = tid;                       // A row (32 halves)
    const int br = tid >> 2, bcb = (tid & 3) * 16;

    for (int k0 = 0; k0 < AHSZ; k0 += 32) {
        {
            const __half2* pa = reinterpret_cast<const __half2*>(
                &Ah0[(size_t)(m0 + ar) * AHSZ + k0]);
            const __half2* pb = reinterpret_cast<const __half2*>(
                &Ah1[(size_t)(m0 + ar) * AHSZ + k0]);
            __half2* dst = reinterpret_cast<__half2*>(&Ash[ar * A_P]);
#pragma unroll
            for (int u = 0; u < 16; u++) dst[u] = __hmul2(pa[u], pb[u]);
        }
        {
            const __half* bp = &B0[(size_t)(k0 + br) * 64 + bcb];
            *reinterpret_cast<uint4*>(&Bsh[br * B_P + bcb]) =
                *reinterpret_cast<const uint4*>(bp);
            *reinterpret_cast<uint4*>(&Bsh[br * B_P + bcb + 8]) =
                *reinterpret_cast<const uint4*>(bp + 8);
        }
        __syncthreads();

#pragma unroll
        for (int kc = 0; kc < 2; kc++) {
            unsigned af[2][4];
#pragma unroll
            for (int mi = 0; mi < 2; mi++)
                ldsm4(af[mi], a_lane[mi] + (unsigned)(kc * 32));
#pragma unroll
            for (int nb = 0; nb < 4; nb++) {
                unsigned kb[4];
                ldsm4t(kb, b_lane + (unsigned)((kc * 16 * B_P + nb * 16) * 2));
#pragma unroll
                for (int mi = 0; mi < 2; mi++) {
                    mma_f16(c[mi][2 * nb],     af[mi], kb[0], kb[1]);
                    mma_f16(c[mi][2 * nb + 1], af[mi], kb[2], kb[3]);
                }
            }
        }
        __syncthreads();
    }

#pragma unroll
    for (int mi = 0; mi < 2; mi++) {
        const int rowA = m0 + w * 32 + mi * 16 + lq;
#pragma unroll
        for (int j = 0; j < 8; j++) {
            const int n = j * 8 + 2 * lr;
            if (n < HK) {
                const float bj0 = bias[n], bj1 = bias[n + 1];
                *reinterpret_cast<float2*>(&Cf[(size_t)rowA * HK + n]) =
                    make_float2(c[mi][j][0] + bj0, c[mi][j][1] + bj1);
                *reinterpret_cast<float2*>(&Cf[(size_t)(rowA + 8) * HK + n]) =
                    make_float2(c[mi][j][2] + bj0, c[mi][j][3] + bj1);
            }
        }
    }
}

// =================== fused flash attention v4 (R11 proven) ===================
#define FQ_P 72
#define KV_STAGE (64*FQ_P*2)
#define FA_SMEM_B (4*KV_STAGE + SS*4)

__global__ void __launch_bounds__(128, 2) fattn_k(
    const __half* __restrict__ qh, const __half* __restrict__ kh, const __half* __restrict__ vh,
    const float* __restrict__ amask, float* __restrict__ scores,
    float* __restrict__ attn, __half* __restrict__ attnh)
{
    extern __shared__ char smc[];
    __half* Qh = (__half*)smc;
    __half* Ksh = (__half*)smc;
    __half* Vsh = (__half*)(smc + 2 * KV_STAGE);
    float* msk = (float*)(smc + 4 * KV_STAGE);

    const int tid  = threadIdx.x;
    const int w    = tid >> 5, lane = tid & 31;
    const int lq   = lane >> 2, lr = lane & 3;
    const int m0   = blockIdx.x * 128;
    const int z    = blockIdx.y, b = z / NH, h = z % NH;

    {
        const float4* s4 = reinterpret_cast<const float4*>(amask + (size_t)b * SS);
        float4* d4 = reinterpret_cast<float4*>(msk);
        for (int i = tid; i < SS / 4; i += 128) d4[i] = s4[i];
    }
    {
        const __half* qp = qh + ((size_t)(b * SS + m0 + tid)) * AHSZ + h * HD;
        uint4* dst = reinterpret_cast<uint4*>(&Qh[tid * FQ_P]);
#pragma unroll
        for (int u = 0; u < 8; u++) dst[u] = *reinterpret_cast<const uint4*>(qp + u * 8);
    }
    __syncthreads();

    unsigned Qa[2][4][4];
#pragma unroll
    for (int mi = 0; mi < 2; mi++) {
        const unsigned q_lane = s2u(Qh) +
            (unsigned)(((w * 32 + mi * 16 + (lane & 15)) * FQ_P + (lane >> 4) * 8) * 2);
#pragma unroll
        for (int kc = 0; kc < 4; kc++) ldsm4(Qa[mi][kc], q_lane + (unsigned)(kc * 32));
    }
    __syncthreads();

    float o[2][8][4];
#pragma unroll
    for (int mi = 0; mi < 2; mi++)
#pragma unroll
        for (int d = 0; d < 8; d++)
#pragma unroll
            for (int r = 0; r < 4; r++) o[mi][d][r] = 0.f;
    float lacc[2][2] = {{0.f, 0.f}, {0.f, 0.f}};

    const __half* kbase = kh + (size_t)b * SS * AHSZ + h * HD;
    const __half* vbase = vh + (size_t)b * SS * AHSZ + h * HD;
    float* sco = scores + (size_t)z * SS * SS;

    const unsigned k_lane_b = s2u(Ksh) +
        (unsigned)((((lane & 15)) * FQ_P + (lane >> 4) * 8) * 2);
    const unsigned v_lane_b = s2u(Vsh) +
        (unsigned)((((lane & 7) + ((lane >> 3) & 1) * 8) * FQ_P + ((lane >> 3) >> 1) * 8) * 2);

    const int sr = tid >> 1;
    const unsigned scb = (unsigned)(tid & 1) * 64u;
    const unsigned k_st = s2u(Ksh) + (unsigned)(sr * FQ_P * 2) + scb;
    const unsigned v_st = s2u(Vsh) + (unsigned)(sr * FQ_P * 2) + scb;
    const int sco_h = (tid & 1) * 32;

    {
        const __half* kp = kbase + (size_t)sr * AHSZ + sco_h;
        const __half* vp = vbase + (size_t)sr * AHSZ + sco_h;
#pragma unroll
        for (int u = 0; u < 4; u++) {
            cpa16(k_st + u * 16, kp + u * 8);
            cpa16(v_st + u * 16, vp + u * 8);
        }
        cpa_commit();
    }

    for (int kt = 0; kt < 32; kt++) {
        const int n0 = kt * 64;
        if (kt < 31) {
            const unsigned s = (unsigned)((kt + 1) & 1) * KV_STAGE;
            const __half* kp = kbase + (size_t)(n0 + 64 + sr) * AHSZ + sco_h;
            const __half* vp = vbase + (size_t)(n0 + 64 + sr) * AHSZ + sco_h;
#pragma unroll
            for (int u = 0; u < 4; u++) {
                cpa16(k_st + s + u * 16, kp + u * 8);
                cpa16(v_st + s + u * 16, vp + u * 8);
            }
            cpa_commit();
            cpa_wait<1>();
        } else {
            cpa_wait<0>();
        }
        __syncthreads();

        const unsigned s = (unsigned)(kt & 1) * KV_STAGE;
        const unsigned k_lane = k_lane_b + s;
        const unsigned v_lane = v_lane_b + s;

#pragma unroll
        for (int kg = 0; kg < 4; kg++) {
            float c[2][2][4];
#pragma unroll
            for (int mi = 0; mi < 2; mi++)
#pragma unroll
                for (int jj = 0; jj < 2; jj++)
#pragma unroll
                    for (int r = 0; r < 4; r++) c[mi][jj][r] = 0.f;
#pragma unroll
            for (int kc = 0; kc < 4; kc++) {
                unsigned kb[4];
                ldsm4(kb, k_lane + (unsigned)((kg * 16 * FQ_P + kc * 16) * 2));
#pragma unroll
                for (int mi = 0; mi < 2; mi++) {
                    mma_f16(c[mi][0], Qa[mi][kc], kb[0], kb[2]);
                    mma_f16(c[mi][1], Qa[mi][kc], kb[1], kb[3]);
                }
            }

            unsigned pa[2][4];
#pragma unroll
            for (int mi = 0; mi < 2; mi++) {
                const int row0 = w * 32 + mi * 16 + lq;
#pragma unroll
                for (int jj = 0; jj < 2; jj++) {
                    const int colL = kg * 16 + jj * 8 + 2 * lr;
                    const float mk0 = msk[n0 + colL], mk1 = msk[n0 + colL + 1];
                    const float s0 = c[mi][jj][0] * 0.125f + mk0;
                    const float s1 = c[mi][jj][1] * 0.125f + mk1;
                    const float s2 = c[mi][jj][2] * 0.125f + mk0;
                    const float s3 = c[mi][jj][3] * 0.125f + mk1;
                    *reinterpret_cast<float2*>(&sco[(size_t)(m0 + row0) * SS + n0 + colL]) =
                        make_float2(s0, s1);
                    *reinterpret_cast<float2*>(&sco[(size_t)(m0 + row0 + 8) * SS + n0 + colL]) =
                        make_float2(s2, s3);
                    const float p0 = __expf(s0), p1 = __expf(s1);
                    const float p2 = __expf(s2), p3 = __expf(s3);
                    lacc[mi][0] += p0 + p1;
                    lacc[mi][1] += p2 + p3;
                    pa[mi][jj * 2 + 0] = pack_f16(p0, p1);
                    pa[mi][jj * 2 + 1] = pack_f16(p2, p3);
                }
            }

#pragma unroll
            for (int dp = 0; dp < 4; dp++) {
                unsigned vb[4];
                ldsm4t(vb, v_lane + (unsigned)((kg * 16 * FQ_P + dp * 16) * 2));
#pragma unroll
                for (int mi = 0; mi < 2; mi++) {
                    mma_f16(o[mi][2 * dp],     pa[mi], vb[0], vb[1]);
                    mma_f16(o[mi][2 * dp + 1], pa[mi], vb[2], vb[3]);
                }
            }
        }
        __syncthreads();
    }

#pragma unroll
    for (int mi = 0; mi < 2; mi++) {
        float l0 = lacc[mi][0], l1 = lacc[mi][1];
        l0 += __shfl_xor_sync(0xFFFFFFFFu, l0, 1);
        l0 += __shfl_xor_sync(0xFFFFFFFFu, l0, 2);
        l1 += __shfl_xor_sync(0xFFFFFFFFu, l1, 1);
        l1 += __shfl_xor_sync(0xFFFFFFFFu, l1, 2);
        const float inv0 = 1.f / l0, inv1 = 1.f / l1;
        const int row0 = w * 32 + mi * 16 + lq;
#pragma unroll
        for (int d = 0; d < 8; d++) {
            const int col = h * HD + d * 8 + 2 * lr;
            const size_t r0 = ((size_t)(b * SS + m0 + row0)) * AHSZ + col;
            const size_t r1 = ((size_t)(b * SS + m0 + row0 + 8)) * AHSZ + col;
            const float v0 = o[mi][d][0] * inv0, v1 = o[mi][d][1] * inv0;
            const float v2 = o[mi][d][2] * inv1, v3 = o[mi][d][3] * inv1;
            *reinterpret_cast<float2*>(&attn[r0]) = make_float2(v0, v1);
            *reinterpret_cast<float2*>(&attn[r1]) = make_float2(v2, v3);
            *reinterpret_cast<unsigned*>(&attnh[r0]) = pack_f16(v0, v1);
            *reinterpret_cast<unsigned*>(&attnh[r1]) = pack_f16(v2, v3);
        }
    }
}

// ---------------- depthwise conv: smem-staged ----------------
#define DW_POS 16
__global__ void __launch_bounds__(384) dwconv_k(const __half* __restrict__ xh,
                                                const float* __restrict__ dwk)
{
    __shared__ __half hsm[(DW_POS + 8) * HIDC];
    const int s0 = blockIdx.x * DW_POS;
    const int b  = blockIdx.y;
    const int tid = threadIdx.x;

    for (int idx = tid; idx < (DW_POS + 8) * (HIDC / 8); idx += 384) {
        const int row = idx / (HIDC / 8);
        const int cb  = (idx % (HIDC / 8)) * 8;
        const int sp  = s0 - 4 + row;
        uint4 val = make_uint4(0, 0, 0, 0);
        if (sp >= 0 && sp < SS)
            val = *reinterpret_cast<const uint4*>(&xh[((size_t)b * SS + sp) * HIDC + cb]);
        *reinterpret_cast<uint4*>(&hsm[row * HIDC + cb]) = val;
    }
    __syncthreads();

    const int c0 = tid * 2;
    float kw0[KW], kw1[KW];
#pragma unroll
    for (int tp = 0; tp < KW; tp++) {
        kw0[tp] = dwk[c0 * KW + tp];
        kw1[tp] = dwk[(c0 + 1) * KW + tp];
    }

    for (int ls = 0; ls < DW_POS; ls++) {
        float a0 = 0.f, a1 = 0.f;
#pragma unroll
        for (int tp = 0; tp < KW; tp++) {
            const float2 xv = __half22float2(
                *reinterpret_cast<const __half2*>(&hsm[(ls + tp) * HIDC + c0]));
            a0 += xv.x * kw0[tp];
            a1 += xv.y * kw1[tp];
        }
        *reinterpret_cast<__half2*>(&g_dwh[((size_t)b * SS + s0 + ls) * HIDC + c0]) =
            __floats2half2_rn(a0, a1);
    }
}

// ---------------- tap softmax + windowed value conv: fp16 v staging ----------------
#define CO_POS 16
__global__ void __launch_bounds__(384) convout_k(const __half* __restrict__ vh)
{
    __shared__ __half vsm[(CO_POS + 8) * AHSZ];
    __shared__ float filt[CO_POS][HK + 2];
    const int s0 = blockIdx.x * CO_POS;
    const int b  = blockIdx.y;
    const int tid = threadIdx.x;

    for (int idx = tid; idx < (CO_POS + 8) * (AHSZ / 8); idx += 384) {
        const int row = idx / (AHSZ / 8);
        const int cb  = (idx % (AHSZ / 8)) * 8;
        const int sp  = s0 - 4 + row;
        uint4 val = make_uint4(0, 0, 0, 0);
        if (sp >= 0 && sp < SS)
            val = *reinterpret_cast<const uint4*>(&vh[((size_t)b * SS + sp) * AHSZ + cb]);
        *reinterpret_cast<uint4*>(&vsm[row * AHSZ + cb]) = val;
    }

    if (tid < CO_POS * NH) {
        const int ls = tid % CO_POS, h = tid / CO_POS;
        const size_t mrow = (size_t)(b * SS + s0 + ls) * HK + h * KW;
        float lg[KW];
        float mx = -1e30f;
#pragma unroll
        for (int i = 0; i < KW; i++) {
            lg[i] = g_logits[mrow + i];
            mx = fmaxf(mx, lg[i]);
        }
        float sum = 0.f;
#pragma unroll
        for (int i = 0; i < KW; i++) { lg[i] = __expf(lg[i] - mx); sum += lg[i]; }
        const float is = 1.f / sum;
#pragma unroll
        for (int i = 0; i < KW; i++) filt[ls][h * KW + i] = lg[i] * is;
    }
    __syncthreads();

    const int c = tid;
    const int hb = (c >> 6) * KW;
    for (int ls = 0; ls < CO_POS; ls++) {
        float acc = 0.f;
#pragma unroll
        for (int tp = 0; tp < KW; tp++)
            acc += __half2float(vsm[(ls + tp) * AHSZ + c]) * filt[ls][hb + tp];
        g_convh[((size_t)(b * SS + s0 + ls)) * AHSZ + c] = __float2half(acc);
    }
}

// ---------------- launch (serial, default stream) ----------------
extern "C" void kernel_launch(void* const* d_in, const int* in_sizes, int n_in,
                              void* d_out, int out_size)
{
    const float* hidden = (const float*)d_in[0];
    const float* amask  = (const float*)d_in[1];
    const float* Wq = (const float*)d_in[2];  const float* bq = (const float*)d_in[3];
    const float* Wk = (const float*)d_in[4];  const float* bk = (const float*)d_in[5];
    const float* Wv = (const float*)d_in[6];  const float* bv = (const float*)d_in[7];
    const float* dwk = (const float*)d_in[8];
    const float* pw  = (const float*)d_in[9]; const float* sepb = (const float*)d_in[10];
    const float* Wak = (const float*)d_in[11]; const float* bak = (const float*)d_in[12];
    const float* Wsl = (const float*)d_in[13]; const float* bsl = (const float*)d_in[14];
    const float* Wcl = (const float*)d_in[15]; const float* bcl = (const float*)d_in[16];

    __half *hidh, *qhp, *khp, *vhp, *dwh, *ksh, *convh, *attnh;
    __half *wqh, *wkh, *wvh, *pwth, *wslh, *wclh, *wakh;
    float *lg, *attn_fb, *sco_fb;
    cudaGetSymbolAddress((void**)&hidh,  g_hidden_h);
    cudaGetSymbolAddress((void**)&qhp,   g_qh);
    cudaGetSymbolAddress((void**)&khp,   g_kh);
    cudaGetSymbolAddress((void**)&vhp,   g_vh);
    cudaGetSymbolAddress((void**)&dwh,   g_dwh);
    cudaGetSymbolAddress((void**)&ksh,   g_ksh);
    cudaGetSymbolAddress((void**)&convh, g_convh);
    cudaGetSymbolAddress((void**)&lg,    g_logits);
    cudaGetSymbolAddress((void**)&attnh, g_attn_h);
    cudaGetSymbolAddress((void**)&wqh,   g_Wq_h);
    cudaGetSymbolAddress((void**)&wkh,   g_Wk_h);
    cudaGetSymbolAddress((void**)&wvh,   g_Wv_h);
    cudaGetSymbolAddress((void**)&pwth,  g_pwt_h);
    cudaGetSymbolAddress((void**)&wslh,  g_Wsl_h);
    cudaGetSymbolAddress((void**)&wclh,  g_Wcl_h);
    cudaGetSymbolAddress((void**)&wakh,  g_Wak_h);
    cudaGetSymbolAddress((void**)&attn_fb, g_attn_fb);
    cudaGetSymbolAddress((void**)&sco_fb,  g_sco_fb);

    float* outp = (float*)d_out;
    const size_t CTX_SZ = (size_t)MROWS * HIDC;
    const size_t ATT_OFF = CTX_SZ;
    const size_t ATT_SZ  = (size_t)MROWS * AHSZ;
    const size_t SCO_OFF = ATT_OFF + ATT_SZ;
    const size_t SCO_SZ  = (size_t)NZ * SS * SS;
    float* attnp = ((size_t)out_size >= ATT_OFF + ATT_SZ) ? outp + ATT_OFF : attn_fb;
    float* scop  = ((size_t)out_size >= SCO_OFF + SCO_SZ) ? outp + SCO_OFF : sco_fb;

    // ---- prep: fused conversions + pw transpose + wak pad ----
    {
        const int n0 = MROWS * HIDC / 4;
        const int nw = HIDC * AHSZ / 4;
        const int nm = AHSZ * AHSZ / 4;
        const int e0 = n0, e1 = e0 + nw, e2 = e1 + nw, e3 = e2 + nw;
        const int e4 = e3 + nm, e5 = e4 + nm;
        cvt_multi<<<(e5 + 255) / 256, 256>>>(
            (const float4*)hidden, (__half2*)hidh, e0,
            (const float4*)Wq,  (__half2*)wqh,  e1,
            (const float4*)Wk,  (__half2*)wkh,  e2,
            (const float4*)Wv,  (__half2*)wvh,  e3,
            (const float4*)Wsl, (__half2*)wslh, e4,
            (const float4*)Wcl, (__half2*)wclh, e5);
    }
    transpose_pw<<<dim3(HIDC / 32, AHSZ / 32), dim3(32, 8)>>>(pw, pwth);
    pad_wak<<<AHSZ, 64>>>(Wak, wakh);

    cudaFuncSetAttribute(fattn_k, cudaFuncAttributeMaxDynamicSharedMemorySize, FA_SMEM_B);

    // 1) fused QKV (fp16 outputs only — no fp32 side copies)
    hgemm<H_QKV><<<dim3(AHSZ / 64, MROWS / 128, 3), 256>>>(
        hidh, nullptr,
        wqh, wkh, wvh, bq, bk, bv,
        nullptr, nullptr, nullptr, qhp, khp, vhp,
        HIDC, HIDC, AHSZ, AHSZ);

    // 2) fused attention v4
    fattn_k<<<dim3(SS / 128, NZ), 128, FA_SMEM_B>>>(qhp, khp, vhp, amask, scop, attnp, attnh);

    // 3) depthwise conv (smem-staged, fp16)
    dwconv_k<<<dim3(SS / DW_POS, BB), 384>>>(hidh, dwk);

    // 4) pointwise: ks = dw @ pw^T + sep_bias (fp16 output)
    hgemm<H_NT><<<dim3(AHSZ / 64, MROWS / 128, 1), 256>>>(
        dwh, nullptr,
        pwth, nullptr, nullptr, sepb, nullptr, nullptr,
        nullptr, nullptr, nullptr, ksh, nullptr, nullptr,
        HIDC, HIDC, AHSZ, AHSZ);

    // 5) filter logits: (ksh*qh) @ Wak + bak (fp16 inputs)
    hgemm_filt<<<dim3(1, MROWS / 128), 128>>>(ksh, qhp, wakh, bak, lg);

    // 6) tap softmax + windowed value conv (fp16 v staging)
    convout_k<<<dim3(SS / CO_POS, BB), 384>>>(vhp);

    // 7) fused mix: context = [attn@Wsl+bsl | conv@Wcl+bcl]
    hgemm<H_MIX><<<dim3(AHSZ / 64, MROWS / 128, 2), 256>>>(
        attnh, convh,
        wslh, wclh, nullptr, bsl, bcl, nullptr,
        outp, nullptr, nullptr, nullptr, nullptr, nullptr,
        AHSZ, AHSZ, AHSZ, HIDC);
}

// round 17
// speedup vs baseline: 1.1107x; 1.0370x over previous
#include <cuda_runtime.h>
#include <cuda_fp16.h>
#include <math.h>
#include <stdint.h>

// ---------------- problem constants ----------------
#define BB    4
#define SS    2048
#define HIDC  768
#define NH    6
#define HD    64
#define AHSZ  384
#define KW    9
#define MROWS (BB*SS)      // 8192
#define NZ    (BB*NH)      // 24
#define HK    (NH*KW)      // 54

// ---------------- scratch ----------------
__device__ __half g_hidden_h[MROWS*HIDC];
__device__ __half g_qh[MROWS*AHSZ];
__device__ __half g_kh[MROWS*AHSZ];
__device__ __half g_vh[MROWS*AHSZ];
__device__ __half g_dwh[MROWS*HIDC];
__device__ __half g_ksh[MROWS*AHSZ];     // fp16 ks (pointwise output)
__device__ __half g_convh[MROWS*AHSZ];
__device__ float  g_logits[MROWS*HK];
__device__ __half g_attn_h[MROWS*AHSZ];
// fp16 weight copies
__device__ __half g_Wq_h[HIDC*AHSZ];
__device__ __half g_Wk_h[HIDC*AHSZ];
__device__ __half g_Wv_h[HIDC*AHSZ];
__device__ __half g_pwt_h[HIDC*AHSZ];    // pw transposed to [c][o]
__device__ __half g_Wsl_h[AHSZ*AHSZ];
__device__ __half g_Wcl_h[AHSZ*AHSZ];
__device__ __half g_Wak_h[AHSZ*64];      // padded 54 -> 64
// fallbacks
__device__ float g_attn_fb[MROWS*AHSZ];
__device__ float g_sco_fb [(size_t)NZ*SS*SS];

// ---------------- mma / ldmatrix / cp.async helpers ----------------
__device__ __forceinline__ void mma_f16(float* d, const unsigned* a, unsigned b0, unsigned b1) {
    asm volatile(
        "mma.sync.aligned.m16n8k16.row.col.f32.f16.f16.f32 "
        "{%0,%1,%2,%3}, {%4,%5,%6,%7}, {%8,%9}, {%0,%1,%2,%3};"
        : "+f"(d[0]), "+f"(d[1]), "+f"(d[2]), "+f"(d[3])
        : "r"(a[0]), "r"(a[1]), "r"(a[2]), "r"(a[3]), "r"(b0), "r"(b1));
}
__device__ __forceinline__ unsigned pack_f16(float lo, float hi) {
    unsigned r;
    asm("cvt.rn.f16x2.f32 %0, %1, %2;" : "=r"(r) : "f"(hi), "f"(lo));
    return r;
}
__device__ __forceinline__ void ldsm4(unsigned* r, unsigned addr) {
    asm volatile("ldmatrix.sync.aligned.m8n8.x4.shared.b16 {%0,%1,%2,%3}, [%4];"
        : "=r"(r[0]), "=r"(r[1]), "=r"(r[2]), "=r"(r[3]) : "r"(addr));
}
__device__ __forceinline__ void ldsm4t(unsigned* r, unsigned addr) {
    asm volatile("ldmatrix.sync.aligned.m8n8.x4.trans.shared.b16 {%0,%1,%2,%3}, [%4];"
        : "=r"(r[0]), "=r"(r[1]), "=r"(r[2]), "=r"(r[3]) : "r"(addr));
}
__device__ __forceinline__ unsigned s2u(const void* p) {
    return (unsigned)__cvta_generic_to_shared(p);
}
__device__ __forceinline__ void cpa16(unsigned dst, const void* src) {
    asm volatile("cp.async.ca.shared.global [%0], [%1], 16;" :: "r"(dst), "l"(src));
}
__device__ __forceinline__ void cpa_commit() { asm volatile("cp.async.commit_group;"); }
template <int N>
__device__ __forceinline__ void cpa_wait() { asm volatile("cp.async.wait_group %0;" :: "n"(N)); }

// ---------------- prep kernels ----------------
__global__ void __launch_bounds__(256) cvt_multi(
    const float4* s0, __half2* d0, int e0,
    const float4* s1, __half2* d1, int e1,
    const float4* s2, __half2* d2, int e2,
    const float4* s3, __half2* d3, int e3,
    const float4* s4, __half2* d4, int e4,
    const float4* s5, __half2* d5, int e5)
{
    const int i = blockIdx.x * 256 + threadIdx.x;
    const float4* s; __half2* d; int base;
    if      (i < e0) { s = s0; d = d0; base = 0;  }
    else if (i < e1) { s = s1; d = d1; base = e0; }
    else if (i < e2) { s = s2; d = d2; base = e1; }
    else if (i < e3) { s = s3; d = d3; base = e2; }
    else if (i < e4) { s = s4; d = d4; base = e3; }
    else if (i < e5) { s = s5; d = d5; base = e4; }
    else return;
    const int j = i - base;
    const float4 x = s[j];
    d[2 * j + 0] = __floats2half2_rn(x.x, x.y);
    d[2 * j + 1] = __floats2half2_rn(x.z, x.w);
}

__global__ void transpose_pw(const float* __restrict__ pw, __half* __restrict__ out)
{
    __shared__ float t[32][33];
    const int c0 = blockIdx.x * 32, o0 = blockIdx.y * 32;
    for (int i = threadIdx.y; i < 32; i += 8)
        t[i][threadIdx.x] = pw[(size_t)(o0 + i) * HIDC + c0 + threadIdx.x];
    __syncthreads();
    for (int i = threadIdx.y; i < 32; i += 8)
        out[(size_t)(c0 + i) * AHSZ + o0 + threadIdx.x] = __float2half(t[threadIdx.x][i]);
}

__global__ void pad_wak(const float* __restrict__ Wak, __half* __restrict__ out)
{
    const int r = blockIdx.x, t = threadIdx.x;  // 384 x 64
    out[r * 64 + t] = (t < HK) ? __float2half(Wak[r * HK + t]) : __half(0.f);
}

// =================== fp16 hgemm (R8/R11-proven): 128x64x32, 256 thr, static smem ===================
enum { H_QKV = 0, H_NT = 1, H_MIX = 3 };
#define A_P 40   // halves pitch of A tile (32+8)
#define B_P 72   // halves pitch of B tile (64+8)

template <int MODE>
__global__ void __launch_bounds__(256) hgemm(
    const __half* __restrict__ Ah0, const __half* __restrict__ Ah1,
    const __half* __restrict__ B0, const __half* __restrict__ B1, const __half* __restrict__ B2,
    const float* __restrict__ b0p, const float* __restrict__ b1p, const float* __restrict__ b2p,
    float* C0f, float* C1f, float* C2f,
    __half* C0h, __half* C1h, __half* C2h,
    int Kdim, int lda, int ldw, int ldc)
{
    __shared__ __half Ash[2][128 * A_P];
    __shared__ __half Bsh[2][32 * B_P];

    const int tid = threadIdx.x;
    const int w = tid >> 5, lane = tid & 31;
    const int lq = lane >> 2, lr = lane & 3;
    const int m0 = blockIdx.y * 128;
    const int n0 = blockIdx.x * 64;

    const __half* A = Ah0;
    const __half* B = B0;
    const float* bias = b0p;
    float* Cf = C0f;
    __half* Ch = C0h;
    if constexpr (MODE == H_QKV) {
        const int z = blockIdx.z;
        B    = (z == 0) ? B0 : ((z == 1) ? B1 : B2);
        bias = (z == 0) ? b0p : ((z == 1) ? b1p : b2p);
        Cf   = (z == 0) ? C0f : ((z == 1) ? C1f : C2f);
        Ch   = (z == 0) ? C0h : ((z == 1) ? C1h : C2h);
    }
    if constexpr (MODE == H_MIX) {
        const int z = blockIdx.z;
        A = z ? Ah1 : Ah0;
        B = z ? B1 : B0;
        bias = z ? b1p : b0p;
        Cf = C0f + z * AHSZ;
        Ch = nullptr;
    }

    float c[8][4];
#pragma unroll
    for (int j = 0; j < 8; j++)
#pragma unroll
        for (int r = 0; r < 4; r++) c[j][r] = 0.f;

    const unsigned a_lane_b = s2u(Ash) +
        (unsigned)(((w * 16 + (lane & 15)) * A_P + (lane >> 4) * 8) * 2);
    const unsigned b_lane_b = s2u(Bsh) +
        (unsigned)((((lane & 7) + ((lane >> 3) & 1) * 8) * B_P + ((lane >> 3) >> 1) * 8) * 2);

    const int ar = tid >> 1, acb = (tid & 1) * 16;
    const int br = tid >> 3, bcb = (tid & 7) * 8;

    const unsigned a_st = s2u(Ash) + (unsigned)((ar * A_P + acb) * 2);
    const unsigned b_st = s2u(Bsh) + (unsigned)((br * B_P + bcb) * 2);
    const unsigned A_STAGE = 128 * A_P * 2;
    const unsigned B_STAGE = 32 * B_P * 2;

    const int NIT = Kdim / 32;
    {
        const __half* ap = &A[(size_t)(m0 + ar) * lda + acb];
        cpa16(a_st, ap);
        cpa16(a_st + 16, ap + 8);
        cpa16(b_st, &B[(size_t)br * ldw + n0 + bcb]);
        cpa_commit();
    }

    for (int it = 0; it < NIT; it++) {
        if (it + 1 < NIT) {
            const int k0 = (it + 1) * 32;
            const unsigned s = (unsigned)((it + 1) & 1);
            const __half* ap = &A[(size_t)(m0 + ar) * lda + k0 + acb];
            cpa16(a_st + s * A_STAGE, ap);
            cpa16(a_st + s * A_STAGE + 16, ap + 8);
            cpa16(b_st + s * B_STAGE, &B[(size_t)(k0 + br) * ldw + n0 + bcb]);
            cpa_commit();
            cpa_wait<1>();
        } else {
            cpa_wait<0>();
        }
        __syncthreads();

        const unsigned s = (unsigned)(it & 1);
        const unsigned a_lane = a_lane_b + s * A_STAGE;
        const unsigned b_lane = b_lane_b + s * B_STAGE;
#pragma unroll
        for (int kc = 0; kc < 2; kc++) {
            unsigned af[4];
            ldsm4(af, a_lane + (unsigned)(kc * 32));
#pragma unroll
            for (int nb = 0; nb < 4; nb++) {
                unsigned kb[4];
                ldsm4t(kb, b_lane + (unsigned)((kc * 16 * B_P + nb * 16) * 2));
                mma_f16(c[2 * nb],     af, kb[0], kb[1]);
                mma_f16(c[2 * nb + 1], af, kb[2], kb[3]);
            }
        }
        __syncthreads();
    }

    // ---- epilogue: fp32 and/or fp16 stores ----
    const int rowA = m0 + w * 16 + lq;
#pragma unroll
    for (int j = 0; j < 8; j++) {
        const int n = n0 + j * 8 + 2 * lr;
        const float bj0 = bias[n], bj1 = bias[n + 1];
        const float v0 = c[j][0] + bj0, v1 = c[j][1] + bj1;
        const float v2 = c[j][2] + bj0, v3 = c[j][3] + bj1;
        if (Cf) {
            *reinterpret_cast<float2*>(&Cf[(size_t)rowA * ldc + n]) = make_float2(v0, v1);
            *reinterpret_cast<float2*>(&Cf[(size_t)(rowA + 8) * ldc + n]) = make_float2(v2, v3);
        }
        if (Ch) {
            *reinterpret_cast<unsigned*>(&Ch[(size_t)rowA * ldc + n]) = pack_f16(v0, v1);
            *reinterpret_cast<unsigned*>(&Ch[(size_t)(rowA + 8) * ldc + n]) = pack_f16(v2, v3);
        }
    }
}

// =================== FILT: (ksh*qh) @ Wak + bak (fp16 inputs, R11 shape) ===================
__global__ void __launch_bounds__(128) hgemm_filt(
    const __half* __restrict__ Ah0, const __half* __restrict__ Ah1,
    const __half* __restrict__ B0, const float* __restrict__ bias, float* __restrict__ Cf)
{
    __shared__ __half Ash[128 * A_P];
    __shared__ __half Bsh[32 * B_P];

    const int tid = threadIdx.x;
    const int w = tid >> 5, lane = tid & 31;
    const int lq = lane >> 2, lr = lane & 3;
    const int m0 = blockIdx.y * 128;

    float c[2][8][4];
#pragma unroll
    for (int mi = 0; mi < 2; mi++)
#pragma unroll
        for (int j = 0; j < 8; j++)
#pragma unroll
            for (int r = 0; r < 4; r++) c[mi][j][r] = 0.f;

    unsigned a_lane[2];
#pragma unroll
    for (int mi = 0; mi < 2; mi++)
        a_lane[mi] = s2u(Ash) +
            (unsigned)(((w * 32 + mi * 16 + (lane & 15)) * A_P + (lane >> 4) * 8) * 2);
    const unsigned b_lane = s2u(Bsh) +
        (unsigned)((((lane & 7) + ((lane >> 3) & 1) * 8) * B_P + ((lane >> 3) >> 1) * 8) * 2);

    const int ar = tid;                       // A row (32 halves)
    const int br = tid >> 2, bcb = (tid & 3) * 16;

    for (int k0 = 0; k0 < AHSZ; k0 += 32) {
        {
            const __half2* pa = reinterpret_cast<const __half2*>(
                &Ah0[(size_t)(m0 + ar) * AHSZ + k0]);
            const __half2* pb = reinterpret_cast<const __half2*>(
                &Ah1[(size_t)(m0 + ar) * AHSZ + k0]);
            __half2* dst = reinterpret_cast<__half2*>(&Ash[ar * A_P]);
#pragma unroll
            for (int u = 0; u < 16; u++) dst[u] = __hmul2(pa[u], pb[u]);
        }
        {
            const __half* bp = &B0[(size_t)(k0 + br) * 64 + bcb];
            *reinterpret_cast<uint4*>(&Bsh[br * B_P + bcb]) =
                *reinterpret_cast<const uint4*>(bp);
            *reinterpret_cast<uint4*>(&Bsh[br * B_P + bcb + 8]) =
                *reinterpret_cast<const uint4*>(bp + 8);
        }
        __syncthreads();

#pragma unroll
        for (int kc = 0; kc < 2; kc++) {
            unsigned af[2][4];
#pragma unroll
            for (int mi = 0; mi < 2; mi++)
                ldsm4(af[mi], a_lane[mi] + (unsigned)(kc * 32));
#pragma unroll
            for (int nb = 0; nb < 4; nb++) {
                unsigned kb[4];
                ldsm4t(kb, b_lane + (unsigned)((kc * 16 * B_P + nb * 16) * 2));
#pragma unroll
                for (int mi = 0; mi < 2; mi++) {
                    mma_f16(c[mi][2 * nb],     af[mi], kb[0], kb[1]);
                    mma_f16(c[mi][2 * nb + 1], af[mi], kb[2], kb[3]);
                }
            }
        }
        __syncthreads();
    }

#pragma unroll
    for (int mi = 0; mi < 2; mi++) {
        const int rowA = m0 + w * 32 + mi * 16 + lq;
#pragma unroll
        for (int j = 0; j < 8; j++) {
            const int n = j * 8 + 2 * lr;
            if (n < HK) {
                const float bj0 = bias[n], bj1 = bias[n + 1];
                *reinterpret_cast<float2*>(&Cf[(size_t)rowA * HK + n]) =
                    make_float2(c[mi][j][0] + bj0, c[mi][j][1] + bj1);
                *reinterpret_cast<float2*>(&Cf[(size_t)(rowA + 8) * HK + n]) =
                    make_float2(c[mi][j][2] + bj0, c[mi][j][3] + bj1);
            }
        }
    }
}

// =================== fused flash attention v5: no smem mask, 3 CTAs/SM target ===================
#define FQ_P 72
#define KV_STAGE (64*FQ_P*2)
#define FA_SMEM_B (4*KV_STAGE)     // 36864 bytes (mask moved to registers/L1)

__global__ void __launch_bounds__(128, 3) fattn_k(
    const __half* __restrict__ qh, const __half* __restrict__ kh, const __half* __restrict__ vh,
    const float* __restrict__ amask, float* __restrict__ scores,
    float* __restrict__ attn, __half* __restrict__ attnh)
{
    extern __shared__ char smc[];
    __half* Qh = (__half*)smc;
    __half* Ksh = (__half*)smc;
    __half* Vsh = (__half*)(smc + 2 * KV_STAGE);

    const int tid  = threadIdx.x;
    const int w    = tid >> 5, lane = tid & 31;
    const int lq   = lane >> 2, lr = lane & 3;
    const int m0   = blockIdx.x * 128;
    const int z    = blockIdx.y, b = z / NH, h = z % NH;

    {
        const __half* qp = qh + ((size_t)(b * SS + m0 + tid)) * AHSZ + h * HD;
        uint4* dst = reinterpret_cast<uint4*>(&Qh[tid * FQ_P]);
#pragma unroll
        for (int u = 0; u < 8; u++) dst[u] = *reinterpret_cast<const uint4*>(qp + u * 8);
    }
    __syncthreads();

    unsigned Qa[2][4][4];
#pragma unroll
    for (int mi = 0; mi < 2; mi++) {
        const unsigned q_lane = s2u(Qh) +
            (unsigned)(((w * 32 + mi * 16 + (lane & 15)) * FQ_P + (lane >> 4) * 8) * 2);
#pragma unroll
        for (int kc = 0; kc < 4; kc++) ldsm4(Qa[mi][kc], q_lane + (unsigned)(kc * 32));
    }
    __syncthreads();

    float o[2][8][4];
#pragma unroll
    for (int mi = 0; mi < 2; mi++)
#pragma unroll
        for (int d = 0; d < 8; d++)
#pragma unroll
            for (int r = 0; r < 4; r++) o[mi][d][r] = 0.f;
    float lacc[2][2] = {{0.f, 0.f}, {0.f, 0.f}};

    const __half* kbase = kh + (size_t)b * SS * AHSZ + h * HD;
    const __half* vbase = vh + (size_t)b * SS * AHSZ + h * HD;
    const float* mbase = amask + (size_t)b * SS;
    float* sco = scores + (size_t)z * SS * SS;

    const unsigned k_lane_b = s2u(Ksh) +
        (unsigned)((((lane & 15)) * FQ_P + (lane >> 4) * 8) * 2);
    const unsigned v_lane_b = s2u(Vsh) +
        (unsigned)((((lane & 7) + ((lane >> 3) & 1) * 8) * FQ_P + ((lane >> 3) >> 1) * 8) * 2);

    const int sr = tid >> 1;
    const unsigned scb = (unsigned)(tid & 1) * 64u;
    const unsigned k_st = s2u(Ksh) + (unsigned)(sr * FQ_P * 2) + scb;
    const unsigned v_st = s2u(Vsh) + (unsigned)(sr * FQ_P * 2) + scb;
    const int sco_h = (tid & 1) * 32;

    {
        const __half* kp = kbase + (size_t)sr * AHSZ + sco_h;
        const __half* vp = vbase + (size_t)sr * AHSZ + sco_h;
#pragma unroll
        for (int u = 0; u < 4; u++) {
            cpa16(k_st + u * 16, kp + u * 8);
            cpa16(v_st + u * 16, vp + u * 8);
        }
        cpa_commit();
    }

    for (int kt = 0; kt < 32; kt++) {
        const int n0 = kt * 64;
        if (kt < 31) {
            const unsigned s = (unsigned)((kt + 1) & 1) * KV_STAGE;
            const __half* kp = kbase + (size_t)(n0 + 64 + sr) * AHSZ + sco_h;
            const __half* vp = vbase + (size_t)(n0 + 64 + sr) * AHSZ + sco_h;
#pragma unroll
            for (int u = 0; u < 4; u++) {
                cpa16(k_st + s + u * 16, kp + u * 8);
                cpa16(v_st + s + u * 16, vp + u * 8);
            }
            cpa_commit();
            cpa_wait<1>();
        } else {
            cpa_wait<0>();
        }
        __syncthreads();

        // per-kt mask values for this lane (8 float2, L1-resident)
        float2 mk[8];
#pragma unroll
        for (int kg = 0; kg < 4; kg++)
#pragma unroll
            for (int jj = 0; jj < 2; jj++)
                mk[kg * 2 + jj] = __ldg(reinterpret_cast<const float2*>(
                    &mbase[n0 + kg * 16 + jj * 8 + 2 * lr]));

        const unsigned s = (unsigned)(kt & 1) * KV_STAGE;
        const unsigned k_lane = k_lane_b + s;
        const unsigned v_lane = v_lane_b + s;

#pragma unroll
        for (int kg = 0; kg < 4; kg++) {
            float c[2][2][4];
#pragma unroll
            for (int mi = 0; mi < 2; mi++)
#pragma unroll
                for (int jj = 0; jj < 2; jj++)
#pragma unroll
                    for (int r = 0; r < 4; r++) c[mi][jj][r] = 0.f;
#pragma unroll
            for (int kc = 0; kc < 4; kc++) {
                unsigned kb[4];
                ldsm4(kb, k_lane + (unsigned)((kg * 16 * FQ_P + kc * 16) * 2));
#pragma unroll
                for (int mi = 0; mi < 2; mi++) {
                    mma_f16(c[mi][0], Qa[mi][kc], kb[0], kb[2]);
                    mma_f16(c[mi][1], Qa[mi][kc], kb[1], kb[3]);
                }
            }

            unsigned pa[2][4];
#pragma unroll
            for (int mi = 0; mi < 2; mi++) {
                const int row0 = w * 32 + mi * 16 + lq;
#pragma unroll
                for (int jj = 0; jj < 2; jj++) {
                    const int colL = kg * 16 + jj * 8 + 2 * lr;
                    const float mk0 = mk[kg * 2 + jj].x, mk1 = mk[kg * 2 + jj].y;
                    const float s0 = c[mi][jj][0] * 0.125f + mk0;
                    const float s1 = c[mi][jj][1] * 0.125f + mk1;
                    const float s2 = c[mi][jj][2] * 0.125f + mk0;
                    const float s3 = c[mi][jj][3] * 0.125f + mk1;
                    __stcs(reinterpret_cast<float2*>(&sco[(size_t)(m0 + row0) * SS + n0 + colL]),
                           make_float2(s0, s1));
                    __stcs(reinterpret_cast<float2*>(&sco[(size_t)(m0 + row0 + 8) * SS + n0 + colL]),
                           make_float2(s2, s3));
                    const float p0 = __expf(s0), p1 = __expf(s1);
                    const float p2 = __expf(s2), p3 = __expf(s3);
                    lacc[mi][0] += p0 + p1;
                    lacc[mi][1] += p2 + p3;
                    pa[mi][jj * 2 + 0] = pack_f16(p0, p1);
                    pa[mi][jj * 2 + 1] = pack_f16(p2, p3);
                }
            }

#pragma unroll
            for (int dp = 0; dp < 4; dp++) {
                unsigned vb[4];
                ldsm4t(vb, v_lane + (unsigned)((kg * 16 * FQ_P + dp * 16) * 2));
#pragma unroll
                for (int mi = 0; mi < 2; mi++) {
                    mma_f16(o[mi][2 * dp],     pa[mi], vb[0], vb[1]);
                    mma_f16(o[mi][2 * dp + 1], pa[mi], vb[2], vb[3]);
                }
            }
        }
        __syncthreads();
    }

#pragma unroll
    for (int mi = 0; mi < 2; mi++) {
        float l0 = lacc[mi][0], l1 = lacc[mi][1];
        l0 += __shfl_xor_sync(0xFFFFFFFFu, l0, 1);
        l0 += __shfl_xor_sync(0xFFFFFFFFu, l0, 2);
        l1 += __shfl_xor_sync(0xFFFFFFFFu, l1, 1);
        l1 += __shfl_xor_sync(0xFFFFFFFFu, l1, 2);
        const float inv0 = 1.f / l0, inv1 = 1.f / l1;
        const int row0 = w * 32 + mi * 16 + lq;
#pragma unroll
        for (int d = 0; d < 8; d++) {
            const int col = h * HD + d * 8 + 2 * lr;
            const size_t r0 = ((size_t)(b * SS + m0 + row0)) * AHSZ + col;
            const size_t r1 = ((size_t)(b * SS + m0 + row0 + 8)) * AHSZ + col;
            const float v0 = o[mi][d][0] * inv0, v1 = o[mi][d][1] * inv0;
            const float v2 = o[mi][d][2] * inv1, v3 = o[mi][d][3] * inv1;
            *reinterpret_cast<float2*>(&attn[r0]) = make_float2(v0, v1);
            *reinterpret_cast<float2*>(&attn[r1]) = make_float2(v2, v3);
            *reinterpret_cast<unsigned*>(&attnh[r0]) = pack_f16(v0, v1);
            *reinterpret_cast<unsigned*>(&attnh[r1]) = pack_f16(v2, v3);
        }
    }
}

// ---------------- depthwise conv: smem-staged ----------------
#define DW_POS 16
__global__ void __launch_bounds__(384) dwconv_k(const __half* __restrict__ xh,
                                                const float* __restrict__ dwk)
{
    __shared__ __half hsm[(DW_POS + 8) * HIDC];
    const int s0 = blockIdx.x * DW_POS;
    const int b  = blockIdx.y;
    const int tid = threadIdx.x;

    for (int idx = tid; idx < (DW_POS + 8) * (HIDC / 8); idx += 384) {
        const int row = idx / (HIDC / 8);
        const int cb  = (idx % (HIDC / 8)) * 8;
        const int sp  = s0 - 4 + row;
        uint4 val = make_uint4(0, 0, 0, 0);
        if (sp >= 0 && sp < SS)
            val = *reinterpret_cast<const uint4*>(&xh[((size_t)b * SS + sp) * HIDC + cb]);
        *reinterpret_cast<uint4*>(&hsm[row * HIDC + cb]) = val;
    }
    __syncthreads();

    const int c0 = tid * 2;
    float kw0[KW], kw1[KW];
#pragma unroll
    for (int tp = 0; tp < KW; tp++) {
        kw0[tp] = dwk[c0 * KW + tp];
        kw1[tp] = dwk[(c0 + 1) * KW + tp];
    }

    for (int ls = 0; ls < DW_POS; ls++) {
        float a0 = 0.f, a1 = 0.f;
#pragma unroll
        for (int tp = 0; tp < KW; tp++) {
            const float2 xv = __half22float2(
                *reinterpret_cast<const __half2*>(&hsm[(ls + tp) * HIDC + c0]));
            a0 += xv.x * kw0[tp];
            a1 += xv.y * kw1[tp];
        }
        *reinterpret_cast<__half2*>(&g_dwh[((size_t)b * SS + s0 + ls) * HIDC + c0]) =
            __floats2half2_rn(a0, a1);
    }
}

// ---------------- tap softmax + windowed value conv: fp16 v staging ----------------
#define CO_POS 16
__global__ void __launch_bounds__(384) convout_k(const __half* __restrict__ vh)
{
    __shared__ __half vsm[(CO_POS + 8) * AHSZ];
    __shared__ float filt[CO_POS][HK + 2];
    const int s0 = blockIdx.x * CO_POS;
    const int b  = blockIdx.y;
    const int tid = threadIdx.x;

    for (int idx = tid; idx < (CO_POS + 8) * (AHSZ / 8); idx += 384) {
        const int row = idx / (AHSZ / 8);
        const int cb  = (idx % (AHSZ / 8)) * 8;
        const int sp  = s0 - 4 + row;
        uint4 val = make_uint4(0, 0, 0, 0);
        if (sp >= 0 && sp < SS)
            val = *reinterpret_cast<const uint4*>(&vh[((size_t)b * SS + sp) * AHSZ + cb]);
        *reinterpret_cast<uint4*>(&vsm[row * AHSZ + cb]) = val;
    }

    if (tid < CO_POS * NH) {
        const int ls = tid % CO_POS, h = tid / CO_POS;
        const size_t mrow = (size_t)(b * SS + s0 + ls) * HK + h * KW;
        float lg[KW];
        float mx = -1e30f;
#pragma unroll
        for (int i = 0; i < KW; i++) {
            lg[i] = g_logits[mrow + i];
            mx = fmaxf(mx, lg[i]);
        }
        float sum = 0.f;
#pragma unroll
        for (int i = 0; i < KW; i++) { lg[i] = __expf(lg[i] - mx); sum += lg[i]; }
        const float is = 1.f / sum;
#pragma unroll
        for (int i = 0; i < KW; i++) filt[ls][h * KW + i] = lg[i] * is;
    }
    __syncthreads();

    const int c = tid;
    const int hb = (c >> 6) * KW;
    for (int ls = 0; ls < CO_POS; ls++) {
        float acc = 0.f;
#pragma unroll
        for (int tp = 0; tp < KW; tp++)
            acc += __half2float(vsm[(ls + tp) * AHSZ + c]) * filt[ls][hb + tp];
        g_convh[((size_t)(b * SS + s0 + ls)) * AHSZ + c] = __float2half(acc);
    }
}

// ---------------- launch (serial, default stream) ----------------
extern "C" void kernel_launch(void* const* d_in, const int* in_sizes, int n_in,
                              void* d_out, int out_size)
{
    const float* hidden = (const float*)d_in[0];
    const float* amask  = (const float*)d_in[1];
    const float* Wq = (const float*)d_in[2];  const float* bq = (const float*)d_in[3];
    const float* Wk = (const float*)d_in[4];  const float* bk = (const float*)d_in[5];
    const float* Wv = (const float*)d_in[6];  const float* bv = (const float*)d_in[7];
    const float* dwk = (const float*)d_in[8];
    const float* pw  = (const float*)d_in[9]; const float* sepb = (const float*)d_in[10];
    const float* Wak = (const float*)d_in[11]; const float* bak = (const float*)d_in[12];
    const float* Wsl = (const float*)d_in[13]; const float* bsl = (const float*)d_in[14];
    const float* Wcl = (const float*)d_in[15]; const float* bcl = (const float*)d_in[16];

    __half *hidh, *qhp, *khp, *vhp, *dwh, *ksh, *convh, *attnh;
    __half *wqh, *wkh, *wvh, *pwth, *wslh, *wclh, *wakh;
    float *lg, *attn_fb, *sco_fb;
    cudaGetSymbolAddress((void**)&hidh,  g_hidden_h);
    cudaGetSymbolAddress((void**)&qhp,   g_qh);
    cudaGetSymbolAddress((void**)&khp,   g_kh);
    cudaGetSymbolAddress((void**)&vhp,   g_vh);
    cudaGetSymbolAddress((void**)&dwh,   g_dwh);
    cudaGetSymbolAddress((void**)&ksh,   g_ksh);
    cudaGetSymbolAddress((void**)&convh, g_convh);
    cudaGetSymbolAddress((void**)&lg,    g_logits);
    cudaGetSymbolAddress((void**)&attnh, g_attn_h);
    cudaGetSymbolAddress((void**)&wqh,   g_Wq_h);
    cudaGetSymbolAddress((void**)&wkh,   g_Wk_h);
    cudaGetSymbolAddress((void**)&wvh,   g_Wv_h);
    cudaGetSymbolAddress((void**)&pwth,  g_pwt_h);
    cudaGetSymbolAddress((void**)&wslh,  g_Wsl_h);
    cudaGetSymbolAddress((void**)&wclh,  g_Wcl_h);
    cudaGetSymbolAddress((void**)&wakh,  g_Wak_h);
    cudaGetSymbolAddress((void**)&attn_fb, g_attn_fb);
    cudaGetSymbolAddress((void**)&sco_fb,  g_sco_fb);

    float* outp = (float*)d_out;
    const size_t CTX_SZ = (size_t)MROWS * HIDC;
    const size_t ATT_OFF = CTX_SZ;
    const size_t ATT_SZ  = (size_t)MROWS * AHSZ;
    const size_t SCO_OFF = ATT_OFF + ATT_SZ;
    const size_t SCO_SZ  = (size_t)NZ * SS * SS;
    float* attnp = ((size_t)out_size >= ATT_OFF + ATT_SZ) ? outp + ATT_OFF : attn_fb;
    float* scop  = ((size_t)out_size >= SCO_OFF + SCO_SZ) ? outp + SCO_OFF : sco_fb;

    // ---- prep: fused conversions + pw transpose + wak pad ----
    {
        const int n0 = MROWS * HIDC / 4;
        const int nw = HIDC * AHSZ / 4;
        const int nm = AHSZ * AHSZ / 4;
        const int e0 = n0, e1 = e0 + nw, e2 = e1 + nw, e3 = e2 + nw;
        const int e4 = e3 + nm, e5 = e4 + nm;
        cvt_multi<<<(e5 + 255) / 256, 256>>>(
            (const float4*)hidden, (__half2*)hidh, e0,
            (const float4*)Wq,  (__half2*)wqh,  e1,
            (const float4*)Wk,  (__half2*)wkh,  e2,
            (const float4*)Wv,  (__half2*)wvh,  e3,
            (const float4*)Wsl, (__half2*)wslh, e4,
            (const float4*)Wcl, (__half2*)wclh, e5);
    }
    transpose_pw<<<dim3(HIDC / 32, AHSZ / 32), dim3(32, 8)>>>(pw, pwth);
    pad_wak<<<AHSZ, 64>>>(Wak, wakh);

    cudaFuncSetAttribute(fattn_k, cudaFuncAttributeMaxDynamicSharedMemorySize, FA_SMEM_B);

    // 1) fused QKV (fp16 outputs only)
    hgemm<H_QKV><<<dim3(AHSZ / 64, MROWS / 128, 3), 256>>>(
        hidh, nullptr,
        wqh, wkh, wvh, bq, bk, bv,
        nullptr, nullptr, nullptr, qhp, khp, vhp,
        HIDC, HIDC, AHSZ, AHSZ);

    // 2) fused attention v5 (3 CTAs/SM, register mask, streaming scores)
    fattn_k<<<dim3(SS / 128, NZ), 128, FA_SMEM_B>>>(qhp, khp, vhp, amask, scop, attnp, attnh);

    // 3) depthwise conv (smem-staged, fp16)
    dwconv_k<<<dim3(SS / DW_POS, BB), 384>>>(hidh, dwk);

    // 4) pointwise: ks = dw @ pw^T + sep_bias (fp16 output)
    hgemm<H_NT><<<dim3(AHSZ / 64, MROWS / 128, 1), 256>>>(
        dwh, nullptr,
        pwth, nullptr, nullptr, sepb, nullptr, nullptr,
        nullptr, nullptr, nullptr, ksh, nullptr, nullptr,
        HIDC, HIDC, AHSZ, AHSZ);

    // 5) filter logits: (ksh*qh) @ Wak + bak (fp16 inputs)
    hgemm_filt<<<dim3(1, MROWS / 128), 128>>>(ksh, qhp, wakh, bak, lg);

    // 6) tap softmax + windowed value conv (fp16 v staging)
    convout_k<<<dim3(SS / CO_POS, BB), 384>>>(vhp);

    // 7) fused mix: context = [attn@Wsl+bsl | conv@Wcl+bcl]
    hgemm<H_MIX><<<dim3(AHSZ / 64, MROWS / 128, 2), 256>>>(
        attnh, convh,
        wslh, wclh, nullptr, bsl, bcl, nullptr,
        outp, nullptr, nullptr, nullptr, nullptr, nullptr,
        AHSZ, AHSZ, AHSZ, HIDC);
}